// round 10
// baseline (speedup 1.0000x reference)
#include <cuda_runtime.h>
#include <cuda_bf16.h>
#include <math.h>

#define BB 8
#define TT 32
#define CC 1024
#define HH 128
#define DST 32
#define FIN 64
#define SS 27            // T - INIT_LENGTH - 1
#define NT 31            // scan steps
#define ROWS (BB*CC)     // 8192

// ================= warp-MMA helpers =================
__device__ __forceinline__ unsigned smem_u32(const void* p){
    unsigned a;
    asm("{ .reg .u64 t; cvta.to.shared.u64 t, %1; cvt.u32.u64 %0, t; }" : "=r"(a) : "l"(p));
    return a;
}

__device__ __forceinline__ void ldsm4(unsigned& r0, unsigned& r1, unsigned& r2, unsigned& r3,
                                      unsigned addr){
    asm volatile("ldmatrix.sync.aligned.m8n8.x4.shared.b16 {%0,%1,%2,%3}, [%4];"
                 : "=r"(r0), "=r"(r1), "=r"(r2), "=r"(r3) : "r"(addr));
}

__device__ __forceinline__ void mma16816(float* c, const unsigned* a, unsigned b0, unsigned b1){
    asm volatile("mma.sync.aligned.m16n8k16.row.col.f32.bf16.bf16.f32 "
                 "{%0,%1,%2,%3}, {%4,%5,%6,%7}, {%8,%9}, {%0,%1,%2,%3};"
                 : "+f"(c[0]), "+f"(c[1]), "+f"(c[2]), "+f"(c[3])
                 : "r"(a[0]), "r"(a[1]), "r"(a[2]), "r"(a[3]), "r"(b0), "r"(b1));
}

__device__ __forceinline__ void cp16(unsigned dst, const void* src){
    asm volatile("cp.async.cg.shared.global [%0], [%1], 16;"
                 :: "r"(dst), "l"(__cvta_generic_to_global(src)));
}
#define CP_COMMIT() asm volatile("cp.async.commit_group;" ::: "memory")
#define CP_WAIT0()  asm volatile("cp.async.wait_group 0;" ::: "memory")

__device__ __forceinline__ unsigned swz(unsigned boff){
    return boff ^ ((boff >> 3) & 0x70);
}

// load rows x K bf16 matrix into k-panel smem layout (panel = 64 k, swizzled 128B rows)
template<int RM, int KD>
__device__ __forceinline__ void load_mat(unsigned dst, const __nv_bfloat16* src, int ld, int tid){
    constexpr int UPR = KD/8;
    constexpr int UNITS = RM*UPR;
    for (int u = tid; u < UNITS; u += 256){
        int row = u / UPR, k8 = u % UPR;
        int kp = k8 >> 3, kc8 = k8 & 7;
        cp16(dst + kp*(RM*128) + swz(row*128 + kc8*16),
             src + (size_t)row*ld + kp*64 + kc8*8);
    }
}

// ---------------- device scratch ----------------
__device__ __nv_bfloat16 g_Lf[(size_t)TT*CC*CC];
__device__ __nv_bfloat16 g_Lb[(size_t)TT*CC*CC];
__device__ __nv_bfloat16 g_BX[(size_t)BB*TT*FIN*CC];   // [b][t][f][c]
__device__ __nv_bfloat16 g_BH[(size_t)BB*HH*CC];       // [b][f][c]

__device__ __nv_bfloat16 g_Zxf[(size_t)NT*ROWS*64];
__device__ __nv_bfloat16 g_Zxb[(size_t)NT*ROWS*64];
__device__ __nv_bfloat16 g_Zhf[(size_t)ROWS*HH];
__device__ __nv_bfloat16 g_Zhb[(size_t)ROWS*HH];
__device__ __nv_bfloat16 g_tmp[(size_t)NT*ROWS*64];
__device__ __nv_bfloat16 g_gi_all[(size_t)NT*ROWS*384];
__device__ __nv_bfloat16 g_gcat[(size_t)ROWS*256];
__device__ float         g_hsf[(size_t)ROWS*HH];
__device__ __nv_bfloat16 g_hsb[(size_t)ROWS*HH];
__device__ float         g_hist[(size_t)SS*ROWS*HH];
__device__ float         g_h[(size_t)ROWS*HH];
__device__ float         g_dinvf[TT*CC];
__device__ float         g_dinvb[TT*CC];
__device__ int           g_mask[CC];

// weights bf16 [N][K]
__device__ __nv_bfloat16 g_Winit[128*64];
__device__ __nv_bfloat16 g_WfeF[32*64];
__device__ __nv_bfloat16 g_WfeB[32*64];
__device__ __nv_bfloat16 g_Wfwd[128*128];
__device__ __nv_bfloat16 g_Wbwd[128*128];
__device__ __nv_bfloat16 g_Wmerge[128*256];
__device__ __nv_bfloat16 g_Wih[384*64];
__device__ __nv_bfloat16 g_Whh[384*128];

#define OFF_INIT  0
#define OFF_FEF   128
#define OFF_FEB   160
#define OFF_FWD   192
#define OFF_BWD   320
#define OFF_MERGE 448
#define OFF_BIH   576
#define OFF_BHH   960
__device__ float g_bias[1344];

// ---------------- prolog kernels ----------------
__global__ void rowsum_kernel(const float* __restrict__ adj){
    int warp = (blockIdx.x*blockDim.x + threadIdx.x) >> 5;
    int lane = threadIdx.x & 31;
    if (warp >= TT*CC) return;
    const float* row = adj + (size_t)warp*CC;
    float s = 0.f;
    for (int j = lane; j < CC; j += 32) s += row[j];
    #pragma unroll
    for (int o = 16; o; o >>= 1) s += __shfl_xor_sync(0xffffffffu, s, o);
    if (!lane) g_dinvf[warp] = 1.0f / sqrtf(s + 1.0f);
}

__global__ void colsum_kernel(const float* __restrict__ adj){
    int t = blockIdx.y;
    int i = blockIdx.x*blockDim.x + threadIdx.x;
    const float* base = adj + (size_t)t*CC*CC + i;
    float s = 0.f;
    for (int j = 0; j < CC; j++) s += base[(size_t)j*CC];
    g_dinvb[t*CC + i] = 1.0f / sqrtf(s + 1.0f);
}

__global__ void build_L_kernel(const float* __restrict__ adj){
    __shared__ float tile[32][33];
    int t = blockIdx.z;
    int i0 = blockIdx.y*32, j0 = blockIdx.x*32;
    int tx = threadIdx.x, ty = threadIdx.y;
    const float* df = g_dinvf + t*CC;
    const float* db = g_dinvb + t*CC;
    #pragma unroll
    for (int r = 0; r < 4; r++){
        int li = ty + r*8;
        int i = i0 + li, j = j0 + tx;
        float v = adj[((size_t)t*CC + i)*CC + j] + ((i == j) ? 1.f : 0.f);
        g_Lf[((size_t)t*CC + i)*CC + j] = __float2bfloat16(v * df[i] * df[j]);
        tile[li][tx] = v * db[i] * db[j];
    }
    __syncthreads();
    #pragma unroll
    for (int r = 0; r < 4; r++){
        int lj = ty + r*8;
        int p = j0 + lj, q = i0 + tx;
        g_Lb[((size_t)t*CC + p)*CC + q] = __float2bfloat16(tile[tx][lj]);
    }
}

__global__ void build_BX_kernel(const float* __restrict__ in){
    __shared__ float tile[32][33];
    int c0 = blockIdx.x*32, f0 = blockIdx.y*32;
    int bt = blockIdx.z;
    int tx = threadIdx.x, ty = threadIdx.y;
    #pragma unroll
    for (int r = 0; r < 4; r++){
        int c = c0 + ty + r*8;
        int f = f0 + tx;
        int col = (f < 32) ? f : 96 + f;
        tile[ty + r*8][tx] = in[(((size_t)bt*CC) + c)*160 + col];
    }
    __syncthreads();
    #pragma unroll
    for (int r = 0; r < 4; r++){
        int f = f0 + ty + r*8;
        int c = c0 + tx;
        g_BX[(((size_t)bt*FIN) + f)*CC + c] = __float2bfloat16(tile[tx][ty + r*8]);
    }
}

__global__ void transpose_h_kernel(){
    __shared__ float tile[32][33];
    int c0 = blockIdx.x*32, f0 = blockIdx.y*32;
    int b = blockIdx.z;
    int tx = threadIdx.x, ty = threadIdx.y;
    #pragma unroll
    for (int r = 0; r < 4; r++){
        int c = c0 + ty + r*8;
        int f = f0 + tx;
        tile[ty + r*8][tx] = g_h[((size_t)b*CC + c)*HH + f];
    }
    __syncthreads();
    #pragma unroll
    for (int r = 0; r < 4; r++){
        int f = f0 + ty + r*8;
        int c = c0 + tx;
        g_BH[((size_t)b*HH + f)*CC + c] = __float2bfloat16(tile[tx][ty + r*8]);
    }
}

__global__ void mask_init_kernel(){
    int i = blockIdx.x*blockDim.x + threadIdx.x;
    if (i < CC) g_mask[i] = 0;
}
__global__ void mask_set_kernel(const int* __restrict__ cells, int n){
    int i = blockIdx.x*blockDim.x + threadIdx.x;
    if (i < n) g_mask[cells[i]] = 1;
}

__global__ void wconv_kernel(const float* __restrict__ W, __nv_bfloat16* w, int K, int N){
    int idx = blockIdx.x*blockDim.x + threadIdx.x;
    if (idx >= N*K) return;
    int n = idx / K, k = idx - n*K;
    w[idx] = __float2bfloat16(W[(size_t)k*N + n]);
}

__global__ void bias_copy_kernel(const float* initb, const float* fef, const float* feb,
                                 const float* fwd, const float* bwd, const float* merge,
                                 const float* bih, const float* bhh){
    int i = blockIdx.x*blockDim.x + threadIdx.x;
    if (i < 128){
        g_bias[OFF_INIT + i] = initb[i];
        g_bias[OFF_FWD + i]  = fwd[i];
        g_bias[OFF_BWD + i]  = bwd[i];
        g_bias[OFF_MERGE + i]= merge[i];
    }
    if (i < 32){
        g_bias[OFF_FEF + i] = fef[i];
        g_bias[OFF_FEB + i] = feb[i];
    }
    if (i < 384){
        g_bias[OFF_BIH + i] = bih[i];
        g_bias[OFF_BHH + i] = bhh[i];
    }
}

// ================ x-propagation: Zx = L @ BX  (M=128, N=64) ================
#define PX_BUFSZ (16384 + 64*128)
#define PX_SMEM  (2*PX_BUFSZ)

__global__ void __launch_bounds__(256) propx_kernel(){
    constexpr int NB = 64;
    constexpr int NCC = NB/32;
    constexpr int TOTAL = 1024 + NB*8;
    extern __shared__ char smem[];
    unsigned smem_base = smem_u32(smem);
    int tid = threadIdx.x;
    int b = blockIdx.x;
    int mtile = blockIdx.y;
    int t = blockIdx.z >> 1;
    int dir = blockIdx.z & 1;

    const __nv_bfloat16* L = (dir ? g_Lb : g_Lf) + (size_t)t*CC*CC + (size_t)mtile*128*CC;
    const __nv_bfloat16* Bsrc = g_BX + (size_t)(b*TT + t)*FIN*CC;
    __nv_bfloat16* Zdst = (dir ? g_Zxb : g_Zxf) + ((size_t)t*ROWS + b*CC + mtile*128)*64;

    int wid = tid >> 5, lane = tid & 31;
    int m0 = (wid >> 1)*32;
    int n0 = (wid & 1)*(NB/2);
    int lrow = lane & 7, lq8 = (lane >> 3) & 1, lkhi = lane >> 4;

    float acc[2][NCC][2][4];
    #pragma unroll
    for (int mi = 0; mi < 2; mi++)
        #pragma unroll
        for (int nc = 0; nc < NCC; nc++)
            #pragma unroll
            for (int sb = 0; sb < 2; sb++)
                #pragma unroll
                for (int q = 0; q < 4; q++) acc[mi][nc][sb][q] = 0.f;

    {
        #pragma unroll
        for (int it = 0; it < TOTAL/256; it++){
            int idx = tid + it*256;
            const __nv_bfloat16* src; unsigned sec; int row, col;
            if (idx < 1024){ row = idx >> 3; col = idx & 7; src = L + (size_t)row*CC + col*8; sec = 0; }
            else { int i2 = idx - 1024; row = i2 >> 3; col = i2 & 7; src = Bsrc + (size_t)row*CC + col*8; sec = 16384; }
            cp16(smem_base + sec + swz(row*128 + col*16), src);
        }
        CP_COMMIT();
    }

    for (int s = 0; s < 16; s++){
        int buf = s & 1;
        if (s + 1 < 16){
            int k0 = (s+1)*64;
            unsigned base = smem_base + (buf^1)*PX_BUFSZ;
            #pragma unroll
            for (int it = 0; it < TOTAL/256; it++){
                int idx = tid + it*256;
                const __nv_bfloat16* src; unsigned sec; int row, col;
                if (idx < 1024){ row = idx >> 3; col = idx & 7; src = L + (size_t)row*CC + k0 + col*8; sec = 0; }
                else { int i2 = idx - 1024; row = i2 >> 3; col = i2 & 7; src = Bsrc + (size_t)row*CC + k0 + col*8; sec = 16384; }
                cp16(base + sec + swz(row*128 + col*16), src);
            }
            CP_COMMIT();
            asm volatile("cp.async.wait_group 1;" ::: "memory");
        } else {
            CP_WAIT0();
        }
        __syncthreads();

        unsigned ab = smem_base + buf*PX_BUFSZ;
        #pragma unroll
        for (int kk = 0; kk < 4; kk++){
            unsigned a[2][4];
            #pragma unroll
            for (int mi = 0; mi < 2; mi++){
                unsigned row = m0 + mi*16 + lrow + lq8*8;
                unsigned sw = swz(row*128 + kk*32 + lkhi*16);
                ldsm4(a[mi][0], a[mi][1], a[mi][2], a[mi][3], ab + sw);
            }
            #pragma unroll
            for (int nc = 0; nc < NCC; nc++){
                unsigned row = n0 + nc*16 + lrow + lq8*8;
                unsigned sw = swz(row*128 + kk*32 + lkhi*16);
                unsigned bh[4];
                ldsm4(bh[0], bh[1], bh[2], bh[3], ab + 16384 + sw);
                #pragma unroll
                for (int mi = 0; mi < 2; mi++){
                    mma16816(acc[mi][nc][0], a[mi], bh[0], bh[2]);
                    mma16816(acc[mi][nc][1], a[mi], bh[1], bh[3]);
                }
            }
        }
        __syncthreads();
    }

    int g = lane >> 2, cpair = (lane & 3)*2;
    #pragma unroll
    for (int mi = 0; mi < 2; mi++){
        int row = m0 + mi*16 + g;
        #pragma unroll
        for (int nc = 0; nc < NCC; nc++){
            #pragma unroll
            for (int sb = 0; sb < 2; sb++){
                int col = n0 + nc*16 + sb*8 + cpair;
                float* cc = acc[mi][nc][sb];
                *(__nv_bfloat162*)(Zdst + (size_t)row*64 + col) =
                    __floats2bfloat162_rn(cc[0], cc[1]);
                *(__nv_bfloat162*)(Zdst + (size_t)(row+8)*64 + col) =
                    __floats2bfloat162_rn(cc[2], cc[3]);
            }
        }
    }
}

// ================ h-propagation: Zh = L @ BH  (M=64 rows/CTA, N=128) ================
#define PH_BUFSZ (8192 + 16384)
#define PH_SMEM  (2*PH_BUFSZ)

__global__ void __launch_bounds__(256) proph_kernel(int t){
    extern __shared__ char smem[];
    unsigned smem_base = smem_u32(smem);
    int tid = threadIdx.x;
    int b = blockIdx.x;
    int mtile = blockIdx.y & 15;
    int dir = blockIdx.y >> 4;

    const __nv_bfloat16* L = (dir ? g_Lb : g_Lf) + (size_t)t*CC*CC + (size_t)mtile*64*CC;
    const __nv_bfloat16* Bsrc = g_BH + (size_t)b*HH*CC;
    __nv_bfloat16* Zdst = (dir ? g_Zhb : g_Zhf) + ((size_t)(b*CC + mtile*64))*HH;

    int wid = tid >> 5, lane = tid & 31;
    int m0 = (wid & 1)*32;
    int n0 = (wid >> 1)*32;
    int lrow = lane & 7, lq8 = (lane >> 3) & 1, lkhi = lane >> 4;

    float acc[2][2][2][4];
    #pragma unroll
    for (int mi = 0; mi < 2; mi++)
        #pragma unroll
        for (int nc = 0; nc < 2; nc++)
            #pragma unroll
            for (int sb = 0; sb < 2; sb++)
                #pragma unroll
                for (int q = 0; q < 4; q++) acc[mi][nc][sb][q] = 0.f;

    {
        #pragma unroll
        for (int it = 0; it < 6; it++){
            int idx = tid + it*256;
            const __nv_bfloat16* src; unsigned sec; int row, col;
            if (idx < 512){ row = idx >> 3; col = idx & 7; src = L + (size_t)row*CC + col*8; sec = 0; }
            else { int i2 = idx - 512; row = i2 >> 3; col = i2 & 7; src = Bsrc + (size_t)row*CC + col*8; sec = 8192; }
            cp16(smem_base + sec + swz(row*128 + col*16), src);
        }
        CP_COMMIT();
    }

    for (int s = 0; s < 16; s++){
        int buf = s & 1;
        if (s + 1 < 16){
            int k0 = (s+1)*64;
            unsigned base = smem_base + (buf^1)*PH_BUFSZ;
            #pragma unroll
            for (int it = 0; it < 6; it++){
                int idx = tid + it*256;
                const __nv_bfloat16* src; unsigned sec; int row, col;
                if (idx < 512){ row = idx >> 3; col = idx & 7; src = L + (size_t)row*CC + k0 + col*8; sec = 0; }
                else { int i2 = idx - 512; row = i2 >> 3; col = i2 & 7; src = Bsrc + (size_t)row*CC + k0 + col*8; sec = 8192; }
                cp16(base + sec + swz(row*128 + col*16), src);
            }
            CP_COMMIT();
            asm volatile("cp.async.wait_group 1;" ::: "memory");
        } else {
            CP_WAIT0();
        }
        __syncthreads();

        unsigned ab = smem_base + buf*PH_BUFSZ;
        #pragma unroll
        for (int kk = 0; kk < 4; kk++){
            unsigned a[2][4];
            #pragma unroll
            for (int mi = 0; mi < 2; mi++){
                unsigned row = m0 + mi*16 + lrow + lq8*8;
                unsigned sw = swz(row*128 + kk*32 + lkhi*16);
                ldsm4(a[mi][0], a[mi][1], a[mi][2], a[mi][3], ab + sw);
            }
            #pragma unroll
            for (int nc = 0; nc < 2; nc++){
                unsigned row = n0 + nc*16 + lrow + lq8*8;
                unsigned sw = swz(row*128 + kk*32 + lkhi*16);
                unsigned bh[4];
                ldsm4(bh[0], bh[1], bh[2], bh[3], ab + 8192 + sw);
                #pragma unroll
                for (int mi = 0; mi < 2; mi++){
                    mma16816(acc[mi][nc][0], a[mi], bh[0], bh[2]);
                    mma16816(acc[mi][nc][1], a[mi], bh[1], bh[3]);
                }
            }
        }
        __syncthreads();
    }

    int g = lane >> 2, cpair = (lane & 3)*2;
    #pragma unroll
    for (int mi = 0; mi < 2; mi++){
        int row = m0 + mi*16 + g;
        #pragma unroll
        for (int nc = 0; nc < 2; nc++){
            #pragma unroll
            for (int sb = 0; sb < 2; sb++){
                int col = n0 + nc*16 + sb*8 + cpair;
                float* cc = acc[mi][nc][sb];
                *(__nv_bfloat162*)(Zdst + (size_t)row*HH + col) =
                    __floats2bfloat162_rn(cc[0], cc[1]);
                *(__nv_bfloat162*)(Zdst + (size_t)(row+8)*HH + col) =
                    __floats2bfloat162_rn(cc[2], cc[3]);
            }
        }
    }
}

// ================ generic bf16 HMMA GEMM (task table) ================
#define SG_BUFSZ 40960
#define SG_SMEM  (2*SG_BUFSZ)

__global__ void __launch_bounds__(256) sgemm_kernel(int basecfg){
    int which = basecfg + blockIdx.y;
    const __nv_bfloat16 *A, *W;
    int lda, K, N, ldc, act = 0;
    const float* bias;
    float* Cf = nullptr;
    __nv_bfloat16 *Cbf = nullptr;

    switch (which){
    case 0: A=g_Zhf; lda=128; K=128; W=g_Wfwd; N=128; bias=g_bias+OFF_FWD;
            Cbf=g_gcat; ldc=256; act=1; break;
    case 1: A=g_Zhb; lda=128; K=128; W=g_Wbwd; N=128; bias=g_bias+OFF_BWD;
            Cbf=g_gcat+128; ldc=256; act=1; break;
    case 2: A=g_gcat; lda=256; K=256; W=g_Wmerge; N=128; bias=g_bias+OFF_MERGE;
            Cf=g_hsf; Cbf=g_hsb; ldc=128; break;
    case 5: A=g_Zxf; lda=64; K=64; W=g_WfeF; N=32; bias=g_bias+OFF_FEF;
            Cbf=g_tmp; ldc=64; act=1; break;
    case 6: A=g_Zxb; lda=64; K=64; W=g_WfeB; N=32; bias=g_bias+OFF_FEB;
            Cbf=g_tmp+32; ldc=64; act=1; break;
    case 7: case 8: {
        int j = which - 7;
        A=g_tmp; lda=64; K=64; W=g_Wih + j*192*64; N=192; bias=g_bias+OFF_BIH+j*192;
        Cbf=g_gi_all + j*192; ldc=384; break; }
    default: // 9: init
        A=g_Zxf; lda=64; K=64; W=g_Winit; N=128; bias=g_bias+OFF_INIT;
        Cf=g_h; ldc=128; act=1; break;
    }

    extern __shared__ char smem[];
    unsigned smem_base = smem_u32(smem);
    int tid = threadIdx.x;
    int mtile = blockIdx.x;
    int wid = tid >> 5, lane = tid & 31;
    int m0 = (wid >> 1)*32;
    int Nw = N >> 1;
    int n0 = (wid & 1)*Nw;
    int ncCount = Nw >> 4; if (ncCount < 1) ncCount = 1;
    int lrow = lane & 7, lq8 = (lane >> 3) & 1, lkhi = lane >> 4;
    int nstages = K >> 6;

    float acc[2][6][2][4];
    #pragma unroll
    for (int mi = 0; mi < 2; mi++)
        #pragma unroll
        for (int nc = 0; nc < 6; nc++)
            #pragma unroll
            for (int sb = 0; sb < 2; sb++)
                #pragma unroll
                for (int q = 0; q < 4; q++) acc[mi][nc][sb][q] = 0.f;

    int total = 1024 + N*8;
    for (int idx = tid; idx < total; idx += 256){
        const __nv_bfloat16* src; unsigned sec; int row, col;
        if (idx < 1024){ row = idx >> 3; col = idx & 7;
            src = A + ((size_t)mtile*128 + row)*lda + col*8; sec = 0; }
        else { int i2 = idx - 1024; row = i2 >> 3; col = i2 & 7;
            src = W + (size_t)row*K + col*8; sec = 16384; }
        cp16(smem_base + sec + swz(row*128 + col*16), src);
    }
    CP_COMMIT();

    for (int s = 0; s < nstages; s++){
        int buf = s & 1;
        if (s + 1 < nstages){
            int k0 = (s+1)*64;
            unsigned base = smem_base + (buf^1)*SG_BUFSZ;
            for (int idx = tid; idx < total; idx += 256){
                const __nv_bfloat16* src; unsigned sec; int row, col;
                if (idx < 1024){ row = idx >> 3; col = idx & 7;
                    src = A + ((size_t)mtile*128 + row)*lda + k0 + col*8; sec = 0; }
                else { int i2 = idx - 1024; row = i2 >> 3; col = i2 & 7;
                    src = W + (size_t)row*K + k0 + col*8; sec = 16384; }
                cp16(base + sec + swz(row*128 + col*16), src);
            }
            CP_COMMIT();
            asm volatile("cp.async.wait_group 1;" ::: "memory");
        } else {
            CP_WAIT0();
        }
        __syncthreads();

        unsigned ab = smem_base + buf*SG_BUFSZ;
        #pragma unroll
        for (int kk = 0; kk < 4; kk++){
            unsigned a[2][4];
            #pragma unroll
            for (int mi = 0; mi < 2; mi++){
                unsigned row = m0 + mi*16 + lrow + lq8*8;
                unsigned sw = swz(row*128 + kk*32 + lkhi*16);
                ldsm4(a[mi][0], a[mi][1], a[mi][2], a[mi][3], ab + sw);
            }
            for (int nc = 0; nc < ncCount; nc++){
                unsigned row = n0 + nc*16 + lrow + lq8*8;
                unsigned sw = swz(row*128 + kk*32 + lkhi*16);
                unsigned bh[4];
                ldsm4(bh[0], bh[1], bh[2], bh[3], ab + 16384 + sw);
                #pragma unroll
                for (int mi = 0; mi < 2; mi++){
                    mma16816(acc[mi][nc][0], a[mi], bh[0], bh[2]);
                    mma16816(acc[mi][nc][1], a[mi], bh[1], bh[3]);
                }
            }
        }
        __syncthreads();
    }

    int g = lane >> 2, cpair = (lane & 3)*2;
    #pragma unroll
    for (int mi = 0; mi < 2; mi++){
        int row = mtile*128 + m0 + mi*16 + g;
        for (int nc = 0; nc < ncCount; nc++){
            #pragma unroll
            for (int sb = 0; sb < 2; sb++){
                int col = n0 + nc*16 + sb*8 + cpair;
                float b0 = bias[col], b1 = bias[col+1];
                float* cc = acc[mi][nc][sb];
                float v00 = cc[0] + b0, v01 = cc[1] + b1;
                float v10 = cc[2] + b0, v11 = cc[3] + b1;
                if (act){
                    v00 = fmaxf(v00, 0.f); v01 = fmaxf(v01, 0.f);
                    v10 = fmaxf(v10, 0.f); v11 = fmaxf(v11, 0.f);
                }
                if (Cf){
                    *(float2*)(Cf + (size_t)row*ldc + col)     = make_float2(v00, v01);
                    *(float2*)(Cf + (size_t)(row+8)*ldc + col) = make_float2(v10, v11);
                }
                if (Cbf){
                    *(__nv_bfloat162*)(Cbf + (size_t)row*ldc + col)     = __floats2bfloat162_rn(v00, v01);
                    *(__nv_bfloat162*)(Cbf + (size_t)(row+8)*ldc + col) = __floats2bfloat162_rn(v10, v11);
                }
            }
        }
    }
}

// ================ ghgru: gh = hs@Whh + bhh; GRU gates; hist + BH write ============
// CTA = 64 rows (128 CTAs). smem: HS[16K] WH[96K] GH(fp32)[96K]; HT reuses WH.
#define GG_HS  0
#define GG_WH  16384
#define GG_GH  114688
#define GG_HT  16384
#define GG_SMEM 212992

__global__ void __launch_bounds__(256) ghgru_kernel(int t){
    extern __shared__ char smem[];
    unsigned sbase = smem_u32(smem);
    int tid = threadIdx.x;
    int row0 = blockIdx.x*64;

    load_mat<64,128>(sbase + GG_HS, g_hsb + (size_t)row0*128, 128, tid);
    load_mat<384,128>(sbase + GG_WH, g_Whh, 128, tid);
    CP_COMMIT(); CP_WAIT0(); __syncthreads();

    int wid = tid >> 5, lane = tid & 31;
    int m0 = (wid & 1)*32;          // 64 rows
    int n0 = (wid >> 1)*96;         // 384 cols
    int lrow = lane & 7, lq8 = (lane >> 3) & 1, lkhi = lane >> 4;
    int g = lane >> 2, cpair = (lane & 3)*2;

    float acc[2][6][2][4];
    #pragma unroll
    for (int mi=0;mi<2;mi++) for (int nc=0;nc<6;nc++) for (int sb=0;sb<2;sb++)
        for (int q=0;q<4;q++) acc[mi][nc][sb][q] = 0.f;

    #pragma unroll
    for (int s = 0; s < 2; s++){
        unsigned aP = sbase + GG_HS + s*8192;
        unsigned wP = sbase + GG_WH + s*49152;
        #pragma unroll
        for (int kk = 0; kk < 4; kk++){
            unsigned a[2][4];
            #pragma unroll
            for (int mi = 0; mi < 2; mi++){
                unsigned row = m0 + mi*16 + lrow + lq8*8;
                ldsm4(a[mi][0], a[mi][1], a[mi][2], a[mi][3],
                      aP + swz(row*128 + kk*32 + lkhi*16));
            }
            #pragma unroll
            for (int nc = 0; nc < 6; nc++){
                unsigned row = n0 + nc*16 + lrow + lq8*8;
                unsigned bh[4];
                ldsm4(bh[0], bh[1], bh[2], bh[3], wP + swz(row*128 + kk*32 + lkhi*16));
                #pragma unroll
                for (int mi = 0; mi < 2; mi++){
                    mma16816(acc[mi][nc][0], a[mi], bh[0], bh[2]);
                    mma16816(acc[mi][nc][1], a[mi], bh[1], bh[3]);
                }
            }
        }
    }
    // epilogue: gh + bhh -> smem fp32
    {
        float* GH = (float*)__cvta_shared_to_generic((unsigned)(sbase + GG_GH));
        const float* bias = g_bias + OFF_BHH;
        #pragma unroll
        for (int mi = 0; mi < 2; mi++){
            int rl = m0 + mi*16 + g;
            #pragma unroll
            for (int nc = 0; nc < 6; nc++){
                #pragma unroll
                for (int sb = 0; sb < 2; sb++){
                    int col = n0 + nc*16 + sb*8 + cpair;
                    float b0 = bias[col], b1 = bias[col+1];
                    float* cc = acc[mi][nc][sb];
                    *(float2*)(GH + rl*384 + col)     = make_float2(cc[0]+b0, cc[1]+b1);
                    *(float2*)(GH + (rl+8)*384 + col) = make_float2(cc[2]+b0, cc[3]+b1);
                }
            }
        }
    }
    __syncthreads();

    // gates: 64 rows x 128 f
    {
        const float* GH = (const float*)__cvta_shared_to_generic((unsigned)(sbase + GG_GH));
        __nv_bfloat16* HT = (__nv_bfloat16*)__cvta_shared_to_generic((unsigned)(sbase + GG_HT));
        #pragma unroll
        for (int it = 0; it < 32; it++){
            int item = tid + it*256;
            int f = item & 127, rl = item >> 7;
            int R = row0 + rl;
            const __nv_bfloat16* gi = g_gi_all + ((size_t)t*ROWS + R)*384;
            float ir = __bfloat162float(gi[f]);
            float iz = __bfloat162float(gi[128 + f]);
            float inn = __bfloat162float(gi[256 + f]);
            float hr = GH[rl*384 + f], hz = GH[rl*384 + 128 + f], hn = GH[rl*384 + 256 + f];
            float rg = 1.f / (1.f + expf(-(ir + hr)));
            float zg = 1.f / (1.f + expf(-(iz + hz)));
            float ng = tanhf(inn + rg*hn);
            float hs = g_hsf[(size_t)R*128 + f];
            float h = (1.f - zg)*ng + zg*hs;
            if (t >= 4) g_hist[((size_t)(t-4)*ROWS + R)*HH + f] = h;
            HT[f*66 + rl] = __float2bfloat16(h);
        }
    }
    __syncthreads();
    // BH write: [b][f][c], coalesced over c
    {
        const __nv_bfloat16* HT = (const __nv_bfloat16*)__cvta_shared_to_generic((unsigned)(sbase + GG_HT));
        int b = row0 >> 10;
        int c0 = row0 & 1023;
        #pragma unroll
        for (int it = 0; it < 32; it++){
            int item = tid + it*256;
            int cl = item & 63, f = item >> 6;
            g_BH[((size_t)b*HH + f)*CC + c0 + cl] = HT[f*66 + cl];
        }
    }
}

// ---------------- final: pred = hist @ outW + outb, fused mask-scatter ----------------
__global__ void __launch_bounds__(256) predout_kernel(const float* __restrict__ in,
                                                      const float* __restrict__ outW,
                                                      const float* __restrict__ outb,
                                                      float* __restrict__ out){
    __shared__ float Ws[128*32];
    __shared__ float As[64*128];
    int r0 = blockIdx.x*64;
    int tid = threadIdx.x;
    for (int i = tid; i < 128*32; i += 256) Ws[i] = outW[i];
    {
        const float4* src = (const float4*)(g_hist + (size_t)r0*HH);
        float4* dst = (float4*)As;
        for (int i = tid; i < 64*128/4; i += 256) dst[i] = src[i];
    }
    __syncthreads();

    #pragma unroll
    for (int it = 0; it < 2; it++){
        int item = tid + it*256;
        int rl = item >> 3;
        int cg = (item & 7)*4;
        float a0 = outb[cg], a1 = outb[cg+1], a2 = outb[cg+2], a3 = outb[cg+3];
        const float* Ar = As + rl*128;
        #pragma unroll 8
        for (int k = 0; k < 128; k++){
            float av = Ar[k];
            const float* wr = Ws + k*32 + cg;
            a0 += av*wr[0]; a1 += av*wr[1]; a2 += av*wr[2]; a3 += av*wr[3];
        }
        int r = r0 + rl;
        int t = r >> 13;
        int rb = r & 8191;
        int b = rb >> 10, c = rb & 1023;
        float4 v;
        if (g_mask[c])
            v = *(const float4*)(in + (((size_t)(b*TT + t + 5)*CC + c)*160) + cg);
        else
            v = make_float4(a0, a1, a2, a3);
        *(float4*)(out + (((size_t)(b*SS + t)*CC + c)*DST) + cg) = v;
    }
}

// ---------------- host orchestration ----------------
static __nv_bfloat16* symb(const void* s){ void* p = nullptr; cudaGetSymbolAddress(&p, s); return (__nv_bfloat16*)p; }

extern "C" void kernel_launch(void* const* d_in, const int* in_sizes, int n_in,
                              void* d_out, int out_size)
{
    const float* inputs   = (const float*)d_in[0];
    const float* adj      = (const float*)d_in[1];
    const float* init_W   = (const float*)d_in[2];
    const float* init_b   = (const float*)d_in[3];
    const float* fe_fwd_W = (const float*)d_in[4];
    const float* fe_fwd_b = (const float*)d_in[5];
    const float* fe_bwd_W = (const float*)d_in[6];
    const float* fe_bwd_b = (const float*)d_in[7];
    const float* fwd_W    = (const float*)d_in[8];
    const float* fwd_b    = (const float*)d_in[9];
    const float* bwd_W    = (const float*)d_in[10];
    const float* bwd_b    = (const float*)d_in[11];
    const float* merge_W  = (const float*)d_in[12];
    const float* merge_b  = (const float*)d_in[13];
    const float* gru_Wih  = (const float*)d_in[14];
    const float* gru_bih  = (const float*)d_in[15];
    const float* gru_Whh  = (const float*)d_in[16];
    const float* gru_bhh  = (const float*)d_in[17];
    const float* out_W    = (const float*)d_in[18];
    const float* out_b    = (const float*)d_in[19];
    const int*   cells    = (const int*)  d_in[20];
    float* out = (float*)d_out;

    cudaFuncSetAttribute(propx_kernel, cudaFuncAttributeMaxDynamicSharedMemorySize, PX_SMEM);
    cudaFuncSetAttribute(proph_kernel, cudaFuncAttributeMaxDynamicSharedMemorySize, PH_SMEM);
    cudaFuncSetAttribute(sgemm_kernel, cudaFuncAttributeMaxDynamicSharedMemorySize, SG_SMEM);
    cudaFuncSetAttribute(ghgru_kernel, cudaFuncAttributeMaxDynamicSharedMemorySize, GG_SMEM);

    // ---- prolog ----
    rowsum_kernel<<<TT*CC/8, 256>>>(adj);
    colsum_kernel<<<dim3(4, TT), 256>>>(adj);
    build_L_kernel<<<dim3(CC/32, CC/32, TT), dim3(32, 8)>>>(adj);
    build_BX_kernel<<<dim3(CC/32, FIN/32, BB*TT), dim3(32, 8)>>>(inputs);
    mask_init_kernel<<<4, 256>>>();
    int nic = in_sizes[20];
    mask_set_kernel<<<(nic + 255)/256, 256>>>(cells, nic);

    wconv_kernel<<<(128*64 + 255)/256, 256>>>(init_W,  symb(g_Winit), 64, 128);
    wconv_kernel<<<(32*64 + 255)/256, 256>>>(fe_fwd_W, symb(g_WfeF),  64, 32);
    wconv_kernel<<<(32*64 + 255)/256, 256>>>(fe_bwd_W, symb(g_WfeB),  64, 32);
    wconv_kernel<<<(128*128 + 255)/256, 256>>>(fwd_W,  symb(g_Wfwd),  128, 128);
    wconv_kernel<<<(128*128 + 255)/256, 256>>>(bwd_W,  symb(g_Wbwd),  128, 128);
    wconv_kernel<<<(128*256 + 255)/256, 256>>>(merge_W,symb(g_Wmerge),256, 128);
    wconv_kernel<<<(384*64 + 255)/256, 256>>>(gru_Wih, symb(g_Wih),   64, 384);
    wconv_kernel<<<(384*128 + 255)/256, 256>>>(gru_Whh,symb(g_Whh),   128, 384);
    bias_copy_kernel<<<2, 256>>>(init_b, fe_fwd_b, fe_bwd_b, fwd_b, bwd_b, merge_b,
                                 gru_bih, gru_bhh);

    // ---- x-dependent precompute ----
    propx_kernel<<<dim3(BB, 8, NT*2), 256, PX_SMEM>>>();
    sgemm_kernel<<<dim3(NT*64, 2), 256, SG_SMEM>>>(5);
    sgemm_kernel<<<dim3(NT*64, 2), 256, SG_SMEM>>>(7);
    sgemm_kernel<<<dim3(64, 1), 256, SG_SMEM>>>(9);
    transpose_h_kernel<<<dim3(CC/32, HH/32, BB), dim3(32, 8)>>>();

    // ---- scan: 4 kernels per step ----
    for (int t = 0; t < NT; t++){
        proph_kernel<<<dim3(BB, 32), 256, PH_SMEM>>>(t);
        sgemm_kernel<<<dim3(64, 2), 256, SG_SMEM>>>(0);   // fwd, bwd -> gcat
        sgemm_kernel<<<dim3(64, 1), 256, SG_SMEM>>>(2);   // merge -> hs
        ghgru_kernel<<<128, 256, GG_SMEM>>>(t);           // gh + gates + BH + hist
    }

    // ---- output ----
    predout_kernel<<<SS*ROWS/64, 256>>>(inputs, out_W, out_b, out);
}

// round 11
// speedup vs baseline: 1.2043x; 1.2043x over previous
#include <cuda_runtime.h>
#include <cuda_bf16.h>
#include <math.h>

#define BB 8
#define TT 32
#define CC 1024
#define HH 128
#define DST 32
#define FIN 64
#define SS 27            // T - INIT_LENGTH - 1
#define NT 31            // scan steps
#define ROWS (BB*CC)     // 8192
#define NCTA 256

// ================= warp-MMA helpers =================
__device__ __forceinline__ unsigned smem_u32(const void* p){
    unsigned a;
    asm("{ .reg .u64 t; cvta.to.shared.u64 t, %1; cvt.u32.u64 %0, t; }" : "=r"(a) : "l"(p));
    return a;
}

__device__ __forceinline__ void ldsm4(unsigned& r0, unsigned& r1, unsigned& r2, unsigned& r3,
                                      unsigned addr){
    asm volatile("ldmatrix.sync.aligned.m8n8.x4.shared.b16 {%0,%1,%2,%3}, [%4];"
                 : "=r"(r0), "=r"(r1), "=r"(r2), "=r"(r3) : "r"(addr));
}

__device__ __forceinline__ void mma16816(float* c, const unsigned* a, unsigned b0, unsigned b1){
    asm volatile("mma.sync.aligned.m16n8k16.row.col.f32.bf16.bf16.f32 "
                 "{%0,%1,%2,%3}, {%4,%5,%6,%7}, {%8,%9}, {%0,%1,%2,%3};"
                 : "+f"(c[0]), "+f"(c[1]), "+f"(c[2]), "+f"(c[3])
                 : "r"(a[0]), "r"(a[1]), "r"(a[2]), "r"(a[3]), "r"(b0), "r"(b1));
}

__device__ __forceinline__ void cp16(unsigned dst, const void* src){
    asm volatile("cp.async.cg.shared.global [%0], [%1], 16;"
                 :: "r"(dst), "l"(__cvta_generic_to_global(src)));
}
#define CP_COMMIT() asm volatile("cp.async.commit_group;" ::: "memory")
#define CP_WAIT0()  asm volatile("cp.async.wait_group 0;" ::: "memory")

__device__ __forceinline__ unsigned swz(unsigned boff){
    return boff ^ ((boff >> 3) & 0x70);
}

// load rows x K bf16 matrix into k-panel smem layout (panel = 64 k, swizzled 128B rows)
template<int RM, int KD>
__device__ __forceinline__ void load_mat(unsigned dst, const __nv_bfloat16* src, int ld, int tid){
    constexpr int UPR = KD/8;
    constexpr int UNITS = RM*UPR;
    for (int u = tid; u < UNITS; u += 256){
        int row = u / UPR, k8 = u % UPR;
        int kp = k8 >> 3, kc8 = k8 & 7;
        cp16(dst + kp*(RM*128) + swz(row*128 + kc8*16),
             src + (size_t)row*ld + kp*64 + kc8*8);
    }
}

// ---------------- device scratch ----------------
__device__ __nv_bfloat16 g_Lf[(size_t)TT*CC*CC];
__device__ __nv_bfloat16 g_Lb[(size_t)TT*CC*CC];
__device__ __nv_bfloat16 g_BX[(size_t)BB*TT*FIN*CC];   // [b][t][f][c]
__device__ __nv_bfloat16 g_BH[(size_t)BB*HH*CC];       // [b][f][c]

__device__ __nv_bfloat16 g_Zxf[(size_t)NT*ROWS*64];
__device__ __nv_bfloat16 g_Zxb[(size_t)NT*ROWS*64];
__device__ __nv_bfloat16 g_Zhf[(size_t)ROWS*HH];
__device__ __nv_bfloat16 g_Zhb[(size_t)ROWS*HH];
__device__ __nv_bfloat16 g_tmp[(size_t)NT*ROWS*64];
__device__ __nv_bfloat16 g_gi_all[(size_t)NT*ROWS*384];
__device__ __nv_bfloat16 g_gcat[(size_t)ROWS*256];
__device__ float         g_hsf[(size_t)ROWS*HH];
__device__ __nv_bfloat16 g_hsb[(size_t)ROWS*HH];
__device__ float         g_hist[(size_t)SS*ROWS*HH];
__device__ float         g_h[(size_t)ROWS*HH];
__device__ float         g_dinvf[TT*CC];
__device__ float         g_dinvb[TT*CC];
__device__ int           g_mask[CC];

__device__ unsigned g_count;
__device__ volatile unsigned g_gen;

// weights bf16 [N][K]
__device__ __nv_bfloat16 g_Winit[128*64];
__device__ __nv_bfloat16 g_WfeF[32*64];
__device__ __nv_bfloat16 g_WfeB[32*64];
__device__ __nv_bfloat16 g_Wfwd[128*128];
__device__ __nv_bfloat16 g_Wbwd[128*128];
__device__ __nv_bfloat16 g_Wmerge[128*256];
__device__ __nv_bfloat16 g_Wih[384*64];
__device__ __nv_bfloat16 g_Whh[384*128];

#define OFF_INIT  0
#define OFF_FEF   128
#define OFF_FEB   160
#define OFF_FWD   192
#define OFF_BWD   320
#define OFF_MERGE 448
#define OFF_BIH   576
#define OFF_BHH   960
__device__ float g_bias[1344];

// ---------------- prolog kernels ----------------
__global__ void rowsum_kernel(const float* __restrict__ adj){
    int warp = (blockIdx.x*blockDim.x + threadIdx.x) >> 5;
    int lane = threadIdx.x & 31;
    if (warp >= TT*CC) return;
    const float* row = adj + (size_t)warp*CC;
    float s = 0.f;
    for (int j = lane; j < CC; j += 32) s += row[j];
    #pragma unroll
    for (int o = 16; o; o >>= 1) s += __shfl_xor_sync(0xffffffffu, s, o);
    if (!lane) g_dinvf[warp] = 1.0f / sqrtf(s + 1.0f);
}

__global__ void colsum_kernel(const float* __restrict__ adj){
    int t = blockIdx.y;
    int i = blockIdx.x*blockDim.x + threadIdx.x;
    const float* base = adj + (size_t)t*CC*CC + i;
    float s = 0.f;
    for (int j = 0; j < CC; j++) s += base[(size_t)j*CC];
    g_dinvb[t*CC + i] = 1.0f / sqrtf(s + 1.0f);
}

__global__ void build_L_kernel(const float* __restrict__ adj){
    __shared__ float tile[32][33];
    int t = blockIdx.z;
    int i0 = blockIdx.y*32, j0 = blockIdx.x*32;
    int tx = threadIdx.x, ty = threadIdx.y;
    const float* df = g_dinvf + t*CC;
    const float* db = g_dinvb + t*CC;
    #pragma unroll
    for (int r = 0; r < 4; r++){
        int li = ty + r*8;
        int i = i0 + li, j = j0 + tx;
        float v = adj[((size_t)t*CC + i)*CC + j] + ((i == j) ? 1.f : 0.f);
        g_Lf[((size_t)t*CC + i)*CC + j] = __float2bfloat16(v * df[i] * df[j]);
        tile[li][tx] = v * db[i] * db[j];
    }
    __syncthreads();
    #pragma unroll
    for (int r = 0; r < 4; r++){
        int lj = ty + r*8;
        int p = j0 + lj, q = i0 + tx;
        g_Lb[((size_t)t*CC + p)*CC + q] = __float2bfloat16(tile[tx][lj]);
    }
}

__global__ void build_BX_kernel(const float* __restrict__ in){
    __shared__ float tile[32][33];
    int c0 = blockIdx.x*32, f0 = blockIdx.y*32;
    int bt = blockIdx.z;
    int tx = threadIdx.x, ty = threadIdx.y;
    #pragma unroll
    for (int r = 0; r < 4; r++){
        int c = c0 + ty + r*8;
        int f = f0 + tx;
        int col = (f < 32) ? f : 96 + f;
        tile[ty + r*8][tx] = in[(((size_t)bt*CC) + c)*160 + col];
    }
    __syncthreads();
    #pragma unroll
    for (int r = 0; r < 4; r++){
        int f = f0 + ty + r*8;
        int c = c0 + tx;
        g_BX[(((size_t)bt*FIN) + f)*CC + c] = __float2bfloat16(tile[tx][ty + r*8]);
    }
}

__global__ void transpose_h_kernel(){
    __shared__ float tile[32][33];
    int c0 = blockIdx.x*32, f0 = blockIdx.y*32;
    int b = blockIdx.z;
    int tx = threadIdx.x, ty = threadIdx.y;
    #pragma unroll
    for (int r = 0; r < 4; r++){
        int c = c0 + ty + r*8;
        int f = f0 + tx;
        tile[ty + r*8][tx] = g_h[((size_t)b*CC + c)*HH + f];
    }
    __syncthreads();
    #pragma unroll
    for (int r = 0; r < 4; r++){
        int f = f0 + ty + r*8;
        int c = c0 + tx;
        g_BH[((size_t)b*HH + f)*CC + c] = __float2bfloat16(tile[tx][ty + r*8]);
    }
}

__global__ void mask_init_kernel(){
    int i = blockIdx.x*blockDim.x + threadIdx.x;
    if (i < CC) g_mask[i] = 0;
}
__global__ void mask_set_kernel(const int* __restrict__ cells, int n){
    int i = blockIdx.x*blockDim.x + threadIdx.x;
    if (i < n) g_mask[cells[i]] = 1;
}

__global__ void wconv_kernel(const float* __restrict__ W, __nv_bfloat16* w, int K, int N){
    int idx = blockIdx.x*blockDim.x + threadIdx.x;
    if (idx >= N*K) return;
    int n = idx / K, k = idx - n*K;
    w[idx] = __float2bfloat16(W[(size_t)k*N + n]);
}

__global__ void bias_copy_kernel(const float* initb, const float* fef, const float* feb,
                                 const float* fwd, const float* bwd, const float* merge,
                                 const float* bih, const float* bhh){
    int i = blockIdx.x*blockDim.x + threadIdx.x;
    if (i < 128){
        g_bias[OFF_INIT + i] = initb[i];
        g_bias[OFF_FWD + i]  = fwd[i];
        g_bias[OFF_BWD + i]  = bwd[i];
        g_bias[OFF_MERGE + i]= merge[i];
    }
    if (i < 32){
        g_bias[OFF_FEF + i] = fef[i];
        g_bias[OFF_FEB + i] = feb[i];
    }
    if (i < 384){
        g_bias[OFF_BIH + i] = bih[i];
        g_bias[OFF_BHH + i] = bhh[i];
    }
}

// ================ x-propagation: Zx = L @ BX  (M=128, N=64) ================
#define PX_BUFSZ (16384 + 64*128)
#define PX_SMEM  (2*PX_BUFSZ)

__global__ void __launch_bounds__(256) propx_kernel(){
    constexpr int NB = 64;
    constexpr int NCC = NB/32;
    constexpr int TOTAL = 1024 + NB*8;
    extern __shared__ char smem[];
    unsigned smem_base = smem_u32(smem);
    int tid = threadIdx.x;
    int b = blockIdx.x;
    int mtile = blockIdx.y;
    int t = blockIdx.z >> 1;
    int dir = blockIdx.z & 1;

    const __nv_bfloat16* L = (dir ? g_Lb : g_Lf) + (size_t)t*CC*CC + (size_t)mtile*128*CC;
    const __nv_bfloat16* Bsrc = g_BX + (size_t)(b*TT + t)*FIN*CC;
    __nv_bfloat16* Zdst = (dir ? g_Zxb : g_Zxf) + ((size_t)t*ROWS + b*CC + mtile*128)*64;

    int wid = tid >> 5, lane = tid & 31;
    int m0 = (wid >> 1)*32;
    int n0 = (wid & 1)*(NB/2);
    int lrow = lane & 7, lq8 = (lane >> 3) & 1, lkhi = lane >> 4;

    float acc[2][NCC][2][4];
    #pragma unroll
    for (int mi = 0; mi < 2; mi++)
        #pragma unroll
        for (int nc = 0; nc < NCC; nc++)
            #pragma unroll
            for (int sb = 0; sb < 2; sb++)
                #pragma unroll
                for (int q = 0; q < 4; q++) acc[mi][nc][sb][q] = 0.f;

    {
        #pragma unroll
        for (int it = 0; it < TOTAL/256; it++){
            int idx = tid + it*256;
            const __nv_bfloat16* src; unsigned sec; int row, col;
            if (idx < 1024){ row = idx >> 3; col = idx & 7; src = L + (size_t)row*CC + col*8; sec = 0; }
            else { int i2 = idx - 1024; row = i2 >> 3; col = i2 & 7; src = Bsrc + (size_t)row*CC + col*8; sec = 16384; }
            cp16(smem_base + sec + swz(row*128 + col*16), src);
        }
        CP_COMMIT();
    }

    for (int s = 0; s < 16; s++){
        int buf = s & 1;
        if (s + 1 < 16){
            int k0 = (s+1)*64;
            unsigned base = smem_base + (buf^1)*PX_BUFSZ;
            #pragma unroll
            for (int it = 0; it < TOTAL/256; it++){
                int idx = tid + it*256;
                const __nv_bfloat16* src; unsigned sec; int row, col;
                if (idx < 1024){ row = idx >> 3; col = idx & 7; src = L + (size_t)row*CC + k0 + col*8; sec = 0; }
                else { int i2 = idx - 1024; row = i2 >> 3; col = i2 & 7; src = Bsrc + (size_t)row*CC + k0 + col*8; sec = 16384; }
                cp16(base + sec + swz(row*128 + col*16), src);
            }
            CP_COMMIT();
            asm volatile("cp.async.wait_group 1;" ::: "memory");
        } else {
            CP_WAIT0();
        }
        __syncthreads();

        unsigned ab = smem_base + buf*PX_BUFSZ;
        #pragma unroll
        for (int kk = 0; kk < 4; kk++){
            unsigned a[2][4];
            #pragma unroll
            for (int mi = 0; mi < 2; mi++){
                unsigned row = m0 + mi*16 + lrow + lq8*8;
                unsigned sw = swz(row*128 + kk*32 + lkhi*16);
                ldsm4(a[mi][0], a[mi][1], a[mi][2], a[mi][3], ab + sw);
            }
            #pragma unroll
            for (int nc = 0; nc < NCC; nc++){
                unsigned row = n0 + nc*16 + lrow + lq8*8;
                unsigned sw = swz(row*128 + kk*32 + lkhi*16);
                unsigned bh[4];
                ldsm4(bh[0], bh[1], bh[2], bh[3], ab + 16384 + sw);
                #pragma unroll
                for (int mi = 0; mi < 2; mi++){
                    mma16816(acc[mi][nc][0], a[mi], bh[0], bh[2]);
                    mma16816(acc[mi][nc][1], a[mi], bh[1], bh[3]);
                }
            }
        }
        __syncthreads();
    }

    int g = lane >> 2, cpair = (lane & 3)*2;
    #pragma unroll
    for (int mi = 0; mi < 2; mi++){
        int row = m0 + mi*16 + g;
        #pragma unroll
        for (int nc = 0; nc < NCC; nc++){
            #pragma unroll
            for (int sb = 0; sb < 2; sb++){
                int col = n0 + nc*16 + sb*8 + cpair;
                float* cc = acc[mi][nc][sb];
                *(__nv_bfloat162*)(Zdst + (size_t)row*64 + col) =
                    __floats2bfloat162_rn(cc[0], cc[1]);
                *(__nv_bfloat162*)(Zdst + (size_t)(row+8)*64 + col) =
                    __floats2bfloat162_rn(cc[2], cc[3]);
            }
        }
    }
}

// ================ generic bf16 HMMA GEMM (precompute tasks) ================
#define SG_BUFSZ 40960
#define SG_SMEM  (2*SG_BUFSZ)

__global__ void __launch_bounds__(256) sgemm_kernel(int basecfg){
    int which = basecfg + blockIdx.y;
    const __nv_bfloat16 *A, *W;
    int lda, K, N, ldc, act = 0;
    const float* bias;
    float* Cf = nullptr;
    __nv_bfloat16 *Cbf = nullptr;

    switch (which){
    case 5: A=g_Zxf; lda=64; K=64; W=g_WfeF; N=32; bias=g_bias+OFF_FEF;
            Cbf=g_tmp; ldc=64; act=1; break;
    case 6: A=g_Zxb; lda=64; K=64; W=g_WfeB; N=32; bias=g_bias+OFF_FEB;
            Cbf=g_tmp+32; ldc=64; act=1; break;
    case 7: case 8: {
        int j = which - 7;
        A=g_tmp; lda=64; K=64; W=g_Wih + j*192*64; N=192; bias=g_bias+OFF_BIH+j*192;
        Cbf=g_gi_all + j*192; ldc=384; break; }
    default: // 9: init
        A=g_Zxf; lda=64; K=64; W=g_Winit; N=128; bias=g_bias+OFF_INIT;
        Cf=g_h; ldc=128; act=1; break;
    }

    extern __shared__ char smem[];
    unsigned smem_base = smem_u32(smem);
    int tid = threadIdx.x;
    int mtile = blockIdx.x;
    int wid = tid >> 5, lane = tid & 31;
    int m0 = (wid >> 1)*32;
    int Nw = N >> 1;
    int n0 = (wid & 1)*Nw;
    int ncCount = Nw >> 4; if (ncCount < 1) ncCount = 1;
    int lrow = lane & 7, lq8 = (lane >> 3) & 1, lkhi = lane >> 4;
    int nstages = K >> 6;

    float acc[2][6][2][4];
    #pragma unroll
    for (int mi = 0; mi < 2; mi++)
        #pragma unroll
        for (int nc = 0; nc < 6; nc++)
            #pragma unroll
            for (int sb = 0; sb < 2; sb++)
                #pragma unroll
                for (int q = 0; q < 4; q++) acc[mi][nc][sb][q] = 0.f;

    int total = 1024 + N*8;
    for (int idx = tid; idx < total; idx += 256){
        const __nv_bfloat16* src; unsigned sec; int row, col;
        if (idx < 1024){ row = idx >> 3; col = idx & 7;
            src = A + ((size_t)mtile*128 + row)*lda + col*8; sec = 0; }
        else { int i2 = idx - 1024; row = i2 >> 3; col = i2 & 7;
            src = W + (size_t)row*K + col*8; sec = 16384; }
        cp16(smem_base + sec + swz(row*128 + col*16), src);
    }
    CP_COMMIT();

    for (int s = 0; s < nstages; s++){
        int buf = s & 1;
        if (s + 1 < nstages){
            int k0 = (s+1)*64;
            unsigned base = smem_base + (buf^1)*SG_BUFSZ;
            for (int idx = tid; idx < total; idx += 256){
                const __nv_bfloat16* src; unsigned sec; int row, col;
                if (idx < 1024){ row = idx >> 3; col = idx & 7;
                    src = A + ((size_t)mtile*128 + row)*lda + k0 + col*8; sec = 0; }
                else { int i2 = idx - 1024; row = i2 >> 3; col = i2 & 7;
                    src = W + (size_t)row*K + k0 + col*8; sec = 16384; }
                cp16(base + sec + swz(row*128 + col*16), src);
            }
            CP_COMMIT();
            asm volatile("cp.async.wait_group 1;" ::: "memory");
        } else {
            CP_WAIT0();
        }
        __syncthreads();

        unsigned ab = smem_base + buf*SG_BUFSZ;
        #pragma unroll
        for (int kk = 0; kk < 4; kk++){
            unsigned a[2][4];
            #pragma unroll
            for (int mi = 0; mi < 2; mi++){
                unsigned row = m0 + mi*16 + lrow + lq8*8;
                unsigned sw = swz(row*128 + kk*32 + lkhi*16);
                ldsm4(a[mi][0], a[mi][1], a[mi][2], a[mi][3], ab + sw);
            }
            for (int nc = 0; nc < ncCount; nc++){
                unsigned row = n0 + nc*16 + lrow + lq8*8;
                unsigned sw = swz(row*128 + kk*32 + lkhi*16);
                unsigned bh[4];
                ldsm4(bh[0], bh[1], bh[2], bh[3], ab + 16384 + sw);
                #pragma unroll
                for (int mi = 0; mi < 2; mi++){
                    mma16816(acc[mi][nc][0], a[mi], bh[0], bh[2]);
                    mma16816(acc[mi][nc][1], a[mi], bh[1], bh[3]);
                }
            }
        }
        __syncthreads();
    }

    int g = lane >> 2, cpair = (lane & 3)*2;
    #pragma unroll
    for (int mi = 0; mi < 2; mi++){
        int row = mtile*128 + m0 + mi*16 + g;
        for (int nc = 0; nc < ncCount; nc++){
            #pragma unroll
            for (int sb = 0; sb < 2; sb++){
                int col = n0 + nc*16 + sb*8 + cpair;
                float b0 = bias[col], b1 = bias[col+1];
                float* cc = acc[mi][nc][sb];
                float v00 = cc[0] + b0, v01 = cc[1] + b1;
                float v10 = cc[2] + b0, v11 = cc[3] + b1;
                if (act){
                    v00 = fmaxf(v00, 0.f); v01 = fmaxf(v01, 0.f);
                    v10 = fmaxf(v10, 0.f); v11 = fmaxf(v11, 0.f);
                }
                if (Cf){
                    *(float2*)(Cf + (size_t)row*ldc + col)     = make_float2(v00, v01);
                    *(float2*)(Cf + (size_t)(row+8)*ldc + col) = make_float2(v10, v11);
                }
                if (Cbf){
                    *(__nv_bfloat162*)(Cbf + (size_t)row*ldc + col)     = __floats2bfloat162_rn(v00, v01);
                    *(__nv_bfloat162*)(Cbf + (size_t)(row+8)*ldc + col) = __floats2bfloat162_rn(v10, v11);
                }
            }
        }
    }
}

// ================ persistent scan kernel ================
// 256 CTAs, 2/SM guaranteed by __launch_bounds__(256,2); smem 90624.
// Phases per step: P(proph) | F(fwd/bwd) | M(merge) | G(gh+gates+BH+hist), grid-synced.
#define SC_SMEM 90624
#define PH_BUFSZ 24576

__device__ __forceinline__ void grid_sync(){
    __threadfence();
    __syncthreads();
    if (threadIdx.x == 0){
        unsigned my = g_gen;
        if (atomicAdd(&g_count, 1) == NCTA - 1){
            atomicExch(&g_count, 0);
            __threadfence();
            g_gen = my + 1;
        } else {
            while (g_gen == my) __nanosleep(64);
        }
        __threadfence();
    }
    __syncthreads();
}

__global__ void __launch_bounds__(256, 2) scan_kernel(){
    extern __shared__ char smem[];
    unsigned sb = smem_u32(smem);
    int tid = threadIdx.x;
    int cta = blockIdx.x;
    int wid = tid >> 5, lane = tid & 31;
    int lrow = lane & 7, lq8 = (lane >> 3) & 1, lkhi = lane >> 4;
    int g = lane >> 2, cpair = (lane & 3)*2;

    for (int t = 0; t < NT; t++){
        // ======== Phase P: Zh = L @ BH ========
        {
            int b = cta >> 5;
            int dir = (cta >> 4) & 1;
            int mtile = cta & 15;
            const __nv_bfloat16* L = (dir ? g_Lb : g_Lf) + (size_t)t*CC*CC + (size_t)mtile*64*CC;
            const __nv_bfloat16* Bsrc = g_BH + (size_t)b*HH*CC;
            __nv_bfloat16* Zdst = (dir ? g_Zhb : g_Zhf) + ((size_t)(b*CC + mtile*64))*HH;

            int m0 = (wid & 1)*32;
            int n0 = (wid >> 1)*32;

            float acc[2][2][2][4];
            #pragma unroll
            for (int mi=0;mi<2;mi++) for (int nc=0;nc<2;nc++) for (int sbq=0;sbq<2;sbq++)
                for (int q=0;q<4;q++) acc[mi][nc][sbq][q] = 0.f;

            {
                #pragma unroll
                for (int it = 0; it < 6; it++){
                    int idx = tid + it*256;
                    const __nv_bfloat16* src; unsigned sec; int row, col;
                    if (idx < 512){ row = idx >> 3; col = idx & 7; src = L + (size_t)row*CC + col*8; sec = 0; }
                    else { int i2 = idx - 512; row = i2 >> 3; col = i2 & 7; src = Bsrc + (size_t)row*CC + col*8; sec = 8192; }
                    cp16(sb + sec + swz(row*128 + col*16), src);
                }
                CP_COMMIT();
            }
            for (int s = 0; s < 16; s++){
                int buf = s & 1;
                if (s + 1 < 16){
                    int k0 = (s+1)*64;
                    unsigned base = sb + (buf^1)*PH_BUFSZ;
                    #pragma unroll
                    for (int it = 0; it < 6; it++){
                        int idx = tid + it*256;
                        const __nv_bfloat16* src; unsigned sec; int row, col;
                        if (idx < 512){ row = idx >> 3; col = idx & 7; src = L + (size_t)row*CC + k0 + col*8; sec = 0; }
                        else { int i2 = idx - 512; row = i2 >> 3; col = i2 & 7; src = Bsrc + (size_t)row*CC + k0 + col*8; sec = 8192; }
                        cp16(base + sec + swz(row*128 + col*16), src);
                    }
                    CP_COMMIT();
                    asm volatile("cp.async.wait_group 1;" ::: "memory");
                } else {
                    CP_WAIT0();
                }
                __syncthreads();

                unsigned ab = sb + buf*PH_BUFSZ;
                #pragma unroll
                for (int kk = 0; kk < 4; kk++){
                    unsigned a[2][4];
                    #pragma unroll
                    for (int mi = 0; mi < 2; mi++){
                        unsigned row = m0 + mi*16 + lrow + lq8*8;
                        ldsm4(a[mi][0], a[mi][1], a[mi][2], a[mi][3],
                              ab + swz(row*128 + kk*32 + lkhi*16));
                    }
                    #pragma unroll
                    for (int nc = 0; nc < 2; nc++){
                        unsigned row = n0 + nc*16 + lrow + lq8*8;
                        unsigned bh[4];
                        ldsm4(bh[0], bh[1], bh[2], bh[3], ab + 8192 + swz(row*128 + kk*32 + lkhi*16));
                        #pragma unroll
                        for (int mi = 0; mi < 2; mi++){
                            mma16816(acc[mi][nc][0], a[mi], bh[0], bh[2]);
                            mma16816(acc[mi][nc][1], a[mi], bh[1], bh[3]);
                        }
                    }
                }
                __syncthreads();
            }
            #pragma unroll
            for (int mi = 0; mi < 2; mi++){
                int row = m0 + mi*16 + g;
                #pragma unroll
                for (int nc = 0; nc < 2; nc++){
                    #pragma unroll
                    for (int sbq = 0; sbq < 2; sbq++){
                        int col = n0 + nc*16 + sbq*8 + cpair;
                        float* cc = acc[mi][nc][sbq];
                        *(__nv_bfloat162*)(Zdst + (size_t)row*HH + col) =
                            __floats2bfloat162_rn(cc[0], cc[1]);
                        *(__nv_bfloat162*)(Zdst + (size_t)(row+8)*HH + col) =
                            __floats2bfloat162_rn(cc[2], cc[3]);
                    }
                }
            }
        }
        grid_sync();

        // ======== Phase F: gcat = relu(Zh @ Wfwd/bwd + b) ========
        {
            int dir = cta >> 7;
            int row0 = (cta & 127)*64;
            const __nv_bfloat16* A = (dir ? g_Zhb : g_Zhf) + (size_t)row0*128;
            const __nv_bfloat16* W = dir ? g_Wbwd : g_Wfwd;
            const float* bias = g_bias + (dir ? OFF_BWD : OFF_FWD);
            load_mat<64,128>(sb + 0,     A, 128, tid);
            load_mat<128,128>(sb + 16384, W, 128, tid);
            CP_COMMIT(); CP_WAIT0(); __syncthreads();

            int m0 = (wid & 1)*32;
            int n0 = (wid >> 1)*32;
            float acc[2][2][2][4];
            #pragma unroll
            for (int mi=0;mi<2;mi++) for (int nc=0;nc<2;nc++) for (int sbq=0;sbq<2;sbq++)
                for (int q=0;q<4;q++) acc[mi][nc][sbq][q] = 0.f;

            #pragma unroll
            for (int s = 0; s < 2; s++){
                unsigned aP = sb + s*8192;
                unsigned wP = sb + 16384 + s*16384;
                #pragma unroll
                for (int kk = 0; kk < 4; kk++){
                    unsigned a[2][4];
                    #pragma unroll
                    for (int mi = 0; mi < 2; mi++){
                        unsigned row = m0 + mi*16 + lrow + lq8*8;
                        ldsm4(a[mi][0], a[mi][1], a[mi][2], a[mi][3],
                              aP + swz(row*128 + kk*32 + lkhi*16));
                    }
                    #pragma unroll
                    for (int nc = 0; nc < 2; nc++){
                        unsigned row = n0 + nc*16 + lrow + lq8*8;
                        unsigned bh[4];
                        ldsm4(bh[0], bh[1], bh[2], bh[3], wP + swz(row*128 + kk*32 + lkhi*16));
                        #pragma unroll
                        for (int mi = 0; mi < 2; mi++){
                            mma16816(acc[mi][nc][0], a[mi], bh[0], bh[2]);
                            mma16816(acc[mi][nc][1], a[mi], bh[1], bh[3]);
                        }
                    }
                }
            }
            #pragma unroll
            for (int mi = 0; mi < 2; mi++){
                int R = row0 + m0 + mi*16 + g;
                #pragma unroll
                for (int nc = 0; nc < 2; nc++){
                    #pragma unroll
                    for (int sbq = 0; sbq < 2; sbq++){
                        int col = n0 + nc*16 + sbq*8 + cpair;
                        float b0 = bias[col], b1 = bias[col+1];
                        float* cc = acc[mi][nc][sbq];
                        float v00 = fmaxf(cc[0]+b0, 0.f), v01 = fmaxf(cc[1]+b1, 0.f);
                        float v10 = fmaxf(cc[2]+b0, 0.f), v11 = fmaxf(cc[3]+b1, 0.f);
                        int gcol = dir*128 + col;
                        *(__nv_bfloat162*)(g_gcat + (size_t)R*256 + gcol)     = __floats2bfloat162_rn(v00, v01);
                        *(__nv_bfloat162*)(g_gcat + (size_t)(R+8)*256 + gcol) = __floats2bfloat162_rn(v10, v11);
                    }
                }
            }
        }
        grid_sync();

        // ======== Phase M: hs = gcat @ Wmerge + b ========
        {
            int row0 = cta*32;
            load_mat<32,256>(sb + 0,      g_gcat + (size_t)row0*256, 256, tid);
            load_mat<128,256>(sb + 16384, g_Wmerge, 256, tid);
            CP_COMMIT(); CP_WAIT0(); __syncthreads();

            int m0 = (wid & 1)*16;
            int n0 = (wid >> 1)*32;
            float acc[2][2][4];
            #pragma unroll
            for (int nc=0;nc<2;nc++) for (int sbq=0;sbq<2;sbq++)
                for (int q=0;q<4;q++) acc[nc][sbq][q] = 0.f;

            #pragma unroll
            for (int s = 0; s < 4; s++){
                unsigned aP = sb + s*4096;
                unsigned wP = sb + 16384 + s*16384;
                #pragma unroll
                for (int kk = 0; kk < 4; kk++){
                    unsigned a[4];
                    unsigned row = m0 + lrow + lq8*8;
                    ldsm4(a[0], a[1], a[2], a[3], aP + swz(row*128 + kk*32 + lkhi*16));
                    #pragma unroll
                    for (int nc = 0; nc < 2; nc++){
                        unsigned wrow = n0 + nc*16 + lrow + lq8*8;
                        unsigned bh[4];
                        ldsm4(bh[0], bh[1], bh[2], bh[3], wP + swz(wrow*128 + kk*32 + lkhi*16));
                        mma16816(acc[nc][0], a, bh[0], bh[2]);
                        mma16816(acc[nc][1], a, bh[1], bh[3]);
                    }
                }
            }
            const float* bias = g_bias + OFF_MERGE;
            int R = row0 + m0 + g;
            #pragma unroll
            for (int nc = 0; nc < 2; nc++){
                #pragma unroll
                for (int sbq = 0; sbq < 2; sbq++){
                    int col = n0 + nc*16 + sbq*8 + cpair;
                    float b0 = bias[col], b1 = bias[col+1];
                    float* cc = acc[nc][sbq];
                    float v00 = cc[0]+b0, v01 = cc[1]+b1;
                    float v10 = cc[2]+b0, v11 = cc[3]+b1;
                    *(float2*)(g_hsf + (size_t)R*128 + col)     = make_float2(v00, v01);
                    *(float2*)(g_hsf + (size_t)(R+8)*128 + col) = make_float2(v10, v11);
                    *(__nv_bfloat162*)(g_hsb + (size_t)R*128 + col)     = __floats2bfloat162_rn(v00, v01);
                    *(__nv_bfloat162*)(g_hsb + (size_t)(R+8)*128 + col) = __floats2bfloat162_rn(v10, v11);
                }
            }
        }
        grid_sync();

        // ======== Phase G: gh = hs @ Whh + b; gates; hist + BH ========
        {
            int row0 = cta*32;
            float* GH = (float*)(smem + 40960);   // [32][388] fp32
            load_mat<32,128>(sb + 0, g_hsb + (size_t)row0*128, 128, tid);
            CP_COMMIT();

            int m0 = (wid & 1)*16;
            int n0 = (wid >> 1)*32;

            for (int chunk = 0; chunk < 3; chunk++){
                load_mat<128,128>(sb + 8192, g_Whh + (size_t)chunk*128*128, 128, tid);
                CP_COMMIT(); CP_WAIT0(); __syncthreads();

                float acc[2][2][4];
                #pragma unroll
                for (int nc=0;nc<2;nc++) for (int sbq=0;sbq<2;sbq++)
                    for (int q=0;q<4;q++) acc[nc][sbq][q] = 0.f;

                #pragma unroll
                for (int s = 0; s < 2; s++){
                    unsigned aP = sb + s*4096;
                    unsigned wP = sb + 8192 + s*16384;
                    #pragma unroll
                    for (int kk = 0; kk < 4; kk++){
                        unsigned a[4];
                        unsigned row = m0 + lrow + lq8*8;
                        ldsm4(a[0], a[1], a[2], a[3], aP + swz(row*128 + kk*32 + lkhi*16));
                        #pragma unroll
                        for (int nc = 0; nc < 2; nc++){
                            unsigned wrow = n0 + nc*16 + lrow + lq8*8;
                            unsigned bh[4];
                            ldsm4(bh[0], bh[1], bh[2], bh[3], wP + swz(wrow*128 + kk*32 + lkhi*16));
                            mma16816(acc[nc][0], a, bh[0], bh[2]);
                            mma16816(acc[nc][1], a, bh[1], bh[3]);
                        }
                    }
                }
                const float* bias = g_bias + OFF_BHH + chunk*128;
                int rl = m0 + g;
                #pragma unroll
                for (int nc = 0; nc < 2; nc++){
                    #pragma unroll
                    for (int sbq = 0; sbq < 2; sbq++){
                        int col = n0 + nc*16 + sbq*8 + cpair;
                        float b0 = bias[col], b1 = bias[col+1];
                        float* cc = acc[nc][sbq];
                        int gcol = chunk*128 + col;
                        *(float2*)(GH + rl*388 + gcol)     = make_float2(cc[0]+b0, cc[1]+b1);
                        *(float2*)(GH + (rl+8)*388 + gcol) = make_float2(cc[2]+b0, cc[3]+b1);
                    }
                }
                __syncthreads();
            }

            // gates: 32 rows x 128 f
            __nv_bfloat16* HT = (__nv_bfloat16*)(smem + 8192);  // [128][33]
            #pragma unroll
            for (int it = 0; it < 16; it++){
                int item = tid + it*256;
                int f = item & 127, rl = item >> 7;
                int R = row0 + rl;
                const __nv_bfloat16* gi = g_gi_all + ((size_t)t*ROWS + R)*384;
                float ir = __bfloat162float(gi[f]);
                float iz = __bfloat162float(gi[128 + f]);
                float inn = __bfloat162float(gi[256 + f]);
                float hr = GH[rl*388 + f], hz = GH[rl*388 + 128 + f], hn = GH[rl*388 + 256 + f];
                float rg = 1.f / (1.f + expf(-(ir + hr)));
                float zg = 1.f / (1.f + expf(-(iz + hz)));
                float ng = tanhf(inn + rg*hn);
                float hs = g_hsf[(size_t)R*128 + f];
                float h = (1.f - zg)*ng + zg*hs;
                if (t >= 4) g_hist[((size_t)(t-4)*ROWS + R)*HH + f] = h;
                HT[f*33 + rl] = __float2bfloat16(h);
            }
            __syncthreads();
            // BH write: [b][f][c], coalesced over c (32 per f)
            {
                int b = row0 >> 10;
                int c0 = row0 & 1023;
                #pragma unroll
                for (int it = 0; it < 16; it++){
                    int item = tid + it*256;
                    int cl = item & 31, f = item >> 5;
                    g_BH[((size_t)b*HH + f)*CC + c0 + cl] = HT[f*33 + cl];
                }
            }
        }
        grid_sync();
    }
}

// ---------------- final: pred = hist @ outW + outb, fused mask-scatter ----------------
__global__ void __launch_bounds__(256) predout_kernel(const float* __restrict__ in,
                                                      const float* __restrict__ outW,
                                                      const float* __restrict__ outb,
                                                      float* __restrict__ out){
    __shared__ float Ws[128*32];
    __shared__ float As[64*128];
    int r0 = blockIdx.x*64;
    int tid = threadIdx.x;
    for (int i = tid; i < 128*32; i += 256) Ws[i] = outW[i];
    {
        const float4* src = (const float4*)(g_hist + (size_t)r0*HH);
        float4* dst = (float4*)As;
        for (int i = tid; i < 64*128/4; i += 256) dst[i] = src[i];
    }
    __syncthreads();

    #pragma unroll
    for (int it = 0; it < 2; it++){
        int item = tid + it*256;
        int rl = item >> 3;
        int cg = (item & 7)*4;
        float a0 = outb[cg], a1 = outb[cg+1], a2 = outb[cg+2], a3 = outb[cg+3];
        const float* Ar = As + rl*128;
        #pragma unroll 8
        for (int k = 0; k < 128; k++){
            float av = Ar[k];
            const float* wr = Ws + k*32 + cg;
            a0 += av*wr[0]; a1 += av*wr[1]; a2 += av*wr[2]; a3 += av*wr[3];
        }
        int r = r0 + rl;
        int t = r >> 13;
        int rb = r & 8191;
        int b = rb >> 10, c = rb & 1023;
        float4 v;
        if (g_mask[c])
            v = *(const float4*)(in + (((size_t)(b*TT + t + 5)*CC + c)*160) + cg);
        else
            v = make_float4(a0, a1, a2, a3);
        *(float4*)(out + (((size_t)(b*SS + t)*CC + c)*DST) + cg) = v;
    }
}

// ---------------- host orchestration ----------------
static __nv_bfloat16* symb(const void* s){ void* p = nullptr; cudaGetSymbolAddress(&p, s); return (__nv_bfloat16*)p; }

extern "C" void kernel_launch(void* const* d_in, const int* in_sizes, int n_in,
                              void* d_out, int out_size)
{
    const float* inputs   = (const float*)d_in[0];
    const float* adj      = (const float*)d_in[1];
    const float* init_W   = (const float*)d_in[2];
    const float* init_b   = (const float*)d_in[3];
    const float* fe_fwd_W = (const float*)d_in[4];
    const float* fe_fwd_b = (const float*)d_in[5];
    const float* fe_bwd_W = (const float*)d_in[6];
    const float* fe_bwd_b = (const float*)d_in[7];
    const float* fwd_W    = (const float*)d_in[8];
    const float* fwd_b    = (const float*)d_in[9];
    const float* bwd_W    = (const float*)d_in[10];
    const float* bwd_b    = (const float*)d_in[11];
    const float* merge_W  = (const float*)d_in[12];
    const float* merge_b  = (const float*)d_in[13];
    const float* gru_Wih  = (const float*)d_in[14];
    const float* gru_bih  = (const float*)d_in[15];
    const float* gru_Whh  = (const float*)d_in[16];
    const float* gru_bhh  = (const float*)d_in[17];
    const float* out_W    = (const float*)d_in[18];
    const float* out_b    = (const float*)d_in[19];
    const int*   cells    = (const int*)  d_in[20];
    float* out = (float*)d_out;

    cudaFuncSetAttribute(propx_kernel, cudaFuncAttributeMaxDynamicSharedMemorySize, PX_SMEM);
    cudaFuncSetAttribute(sgemm_kernel, cudaFuncAttributeMaxDynamicSharedMemorySize, SG_SMEM);
    cudaFuncSetAttribute(scan_kernel,  cudaFuncAttributeMaxDynamicSharedMemorySize, SC_SMEM);

    // ---- prolog ----
    rowsum_kernel<<<TT*CC/8, 256>>>(adj);
    colsum_kernel<<<dim3(4, TT), 256>>>(adj);
    build_L_kernel<<<dim3(CC/32, CC/32, TT), dim3(32, 8)>>>(adj);
    build_BX_kernel<<<dim3(CC/32, FIN/32, BB*TT), dim3(32, 8)>>>(inputs);
    mask_init_kernel<<<4, 256>>>();
    int nic = in_sizes[20];
    mask_set_kernel<<<(nic + 255)/256, 256>>>(cells, nic);

    wconv_kernel<<<(128*64 + 255)/256, 256>>>(init_W,  symb(g_Winit), 64, 128);
    wconv_kernel<<<(32*64 + 255)/256, 256>>>(fe_fwd_W, symb(g_WfeF),  64, 32);
    wconv_kernel<<<(32*64 + 255)/256, 256>>>(fe_bwd_W, symb(g_WfeB),  64, 32);
    wconv_kernel<<<(128*128 + 255)/256, 256>>>(fwd_W,  symb(g_Wfwd),  128, 128);
    wconv_kernel<<<(128*128 + 255)/256, 256>>>(bwd_W,  symb(g_Wbwd),  128, 128);
    wconv_kernel<<<(128*256 + 255)/256, 256>>>(merge_W,symb(g_Wmerge),256, 128);
    wconv_kernel<<<(384*64 + 255)/256, 256>>>(gru_Wih, symb(g_Wih),   64, 384);
    wconv_kernel<<<(384*128 + 255)/256, 256>>>(gru_Whh,symb(g_Whh),   128, 384);
    bias_copy_kernel<<<2, 256>>>(init_b, fe_fwd_b, fe_bwd_b, fwd_b, bwd_b, merge_b,
                                 gru_bih, gru_bhh);

    // ---- x-dependent precompute ----
    propx_kernel<<<dim3(BB, 8, NT*2), 256, PX_SMEM>>>();
    sgemm_kernel<<<dim3(NT*64, 2), 256, SG_SMEM>>>(5);
    sgemm_kernel<<<dim3(NT*64, 2), 256, SG_SMEM>>>(7);
    sgemm_kernel<<<dim3(64, 1), 256, SG_SMEM>>>(9);
    transpose_h_kernel<<<dim3(CC/32, HH/32, BB), dim3(32, 8)>>>();

    // ---- persistent scan (all 31 steps, 1 launch) ----
    scan_kernel<<<NCTA, 256, SC_SMEM>>>();

    // ---- output ----
    predout_kernel<<<SS*ROWS/64, 256>>>(inputs, out_W, out_b, out);
}

// round 12
// speedup vs baseline: 1.3224x; 1.0981x over previous
#include <cuda_runtime.h>
#include <cuda_bf16.h>
#include <math.h>

#define BB 8
#define TT 32
#define CC 1024
#define HH 128
#define DST 32
#define FIN 64
#define SS 27            // T - INIT_LENGTH - 1
#define NT 31            // scan steps
#define ROWS (BB*CC)     // 8192

// ================= warp-MMA helpers =================
__device__ __forceinline__ unsigned smem_u32(const void* p){
    unsigned a;
    asm("{ .reg .u64 t; cvta.to.shared.u64 t, %1; cvt.u32.u64 %0, t; }" : "=r"(a) : "l"(p));
    return a;
}

__device__ __forceinline__ void ldsm4(unsigned& r0, unsigned& r1, unsigned& r2, unsigned& r3,
                                      unsigned addr){
    asm volatile("ldmatrix.sync.aligned.m8n8.x4.shared.b16 {%0,%1,%2,%3}, [%4];"
                 : "=r"(r0), "=r"(r1), "=r"(r2), "=r"(r3) : "r"(addr));
}

__device__ __forceinline__ void mma16816(float* c, const unsigned* a, unsigned b0, unsigned b1){
    asm volatile("mma.sync.aligned.m16n8k16.row.col.f32.bf16.bf16.f32 "
                 "{%0,%1,%2,%3}, {%4,%5,%6,%7}, {%8,%9}, {%0,%1,%2,%3};"
                 : "+f"(c[0]), "+f"(c[1]), "+f"(c[2]), "+f"(c[3])
                 : "r"(a[0]), "r"(a[1]), "r"(a[2]), "r"(a[3]), "r"(b0), "r"(b1));
}

__device__ __forceinline__ void cp16(unsigned dst, const void* src){
    asm volatile("cp.async.cg.shared.global [%0], [%1], 16;"
                 :: "r"(dst), "l"(__cvta_generic_to_global(src)));
}
#define CP_COMMIT() asm volatile("cp.async.commit_group;" ::: "memory")
#define CP_WAIT0()  asm volatile("cp.async.wait_group 0;" ::: "memory")

__device__ __forceinline__ unsigned swz(unsigned boff){
    return boff ^ ((boff >> 3) & 0x70);
}

// ---------------- device scratch ----------------
__device__ __nv_bfloat16 g_Lf[(size_t)TT*CC*CC];
__device__ __nv_bfloat16 g_Lb[(size_t)TT*CC*CC];
__device__ __nv_bfloat16 g_BX[(size_t)BB*TT*FIN*CC];   // [b][t][f][c]
__device__ __nv_bfloat16 g_BH[(size_t)BB*HH*CC];       // [b][f][c]

__device__ __nv_bfloat16 g_Zxf[(size_t)NT*ROWS*64];
__device__ __nv_bfloat16 g_Zxb[(size_t)NT*ROWS*64];
__device__ __nv_bfloat16 g_Zhf[(size_t)ROWS*HH];
__device__ __nv_bfloat16 g_Zhb[(size_t)ROWS*HH];
__device__ __nv_bfloat16 g_tmp[(size_t)NT*ROWS*64];
__device__ __nv_bfloat16 g_gi_all[(size_t)NT*ROWS*384];
__device__ __nv_bfloat16 g_gcat[(size_t)ROWS*256];
__device__ float         g_hsf[(size_t)ROWS*HH];
__device__ float         g_gh[(size_t)ROWS*384];
__device__ float         g_hist[(size_t)SS*ROWS*HH];
__device__ float         g_h[(size_t)ROWS*HH];
__device__ float         g_dinvf[TT*CC];
__device__ float         g_dinvb[TT*CC];
__device__ int           g_mask[CC];

// weights bf16 [N][K]
__device__ __nv_bfloat16 g_Winit[128*64];
__device__ __nv_bfloat16 g_WfeF[32*64];
__device__ __nv_bfloat16 g_WfeB[32*64];
__device__ __nv_bfloat16 g_Wfwd[128*128];
__device__ __nv_bfloat16 g_Wbwd[128*128];
__device__ __nv_bfloat16 g_Wmerge[128*256];
__device__ __nv_bfloat16 g_Wmh[384*256];     // (Wmerge @ Whh)^T, bf16 [N][K]
__device__ __nv_bfloat16 g_Wih[384*64];
__device__ float         g_bias2[384];       // bm @ Whh + bhh

#define OFF_INIT  0
#define OFF_FEF   128
#define OFF_FEB   160
#define OFF_FWD   192
#define OFF_BWD   320
#define OFF_MERGE 448
#define OFF_BIH   576
__device__ float g_bias[960];

// ---------------- prolog kernels ----------------
__global__ void rowsum_kernel(const float* __restrict__ adj){
    int warp = (blockIdx.x*blockDim.x + threadIdx.x) >> 5;
    int lane = threadIdx.x & 31;
    if (warp >= TT*CC) return;
    const float* row = adj + (size_t)warp*CC;
    float s = 0.f;
    for (int j = lane; j < CC; j += 32) s += row[j];
    #pragma unroll
    for (int o = 16; o; o >>= 1) s += __shfl_xor_sync(0xffffffffu, s, o);
    if (!lane) g_dinvf[warp] = 1.0f / sqrtf(s + 1.0f);
}

__global__ void colsum_kernel(const float* __restrict__ adj){
    int t = blockIdx.y;
    int i = blockIdx.x*blockDim.x + threadIdx.x;
    const float* base = adj + (size_t)t*CC*CC + i;
    float s = 0.f;
    for (int j = 0; j < CC; j++) s += base[(size_t)j*CC];
    g_dinvb[t*CC + i] = 1.0f / sqrtf(s + 1.0f);
}

__global__ void build_L_kernel(const float* __restrict__ adj){
    __shared__ float tile[32][33];
    int t = blockIdx.z;
    int i0 = blockIdx.y*32, j0 = blockIdx.x*32;
    int tx = threadIdx.x, ty = threadIdx.y;
    const float* df = g_dinvf + t*CC;
    const float* db = g_dinvb + t*CC;
    #pragma unroll
    for (int r = 0; r < 4; r++){
        int li = ty + r*8;
        int i = i0 + li, j = j0 + tx;
        float v = adj[((size_t)t*CC + i)*CC + j] + ((i == j) ? 1.f : 0.f);
        g_Lf[((size_t)t*CC + i)*CC + j] = __float2bfloat16(v * df[i] * df[j]);
        tile[li][tx] = v * db[i] * db[j];
    }
    __syncthreads();
    #pragma unroll
    for (int r = 0; r < 4; r++){
        int lj = ty + r*8;
        int p = j0 + lj, q = i0 + tx;
        g_Lb[((size_t)t*CC + p)*CC + q] = __float2bfloat16(tile[tx][lj]);
    }
}

__global__ void build_BX_kernel(const float* __restrict__ in){
    __shared__ float tile[32][33];
    int c0 = blockIdx.x*32, f0 = blockIdx.y*32;
    int bt = blockIdx.z;
    int tx = threadIdx.x, ty = threadIdx.y;
    #pragma unroll
    for (int r = 0; r < 4; r++){
        int c = c0 + ty + r*8;
        int f = f0 + tx;
        int col = (f < 32) ? f : 96 + f;
        tile[ty + r*8][tx] = in[(((size_t)bt*CC) + c)*160 + col];
    }
    __syncthreads();
    #pragma unroll
    for (int r = 0; r < 4; r++){
        int f = f0 + ty + r*8;
        int c = c0 + tx;
        g_BX[(((size_t)bt*FIN) + f)*CC + c] = __float2bfloat16(tile[tx][ty + r*8]);
    }
}

__global__ void transpose_h_kernel(){
    __shared__ float tile[32][33];
    int c0 = blockIdx.x*32, f0 = blockIdx.y*32;
    int b = blockIdx.z;
    int tx = threadIdx.x, ty = threadIdx.y;
    #pragma unroll
    for (int r = 0; r < 4; r++){
        int c = c0 + ty + r*8;
        int f = f0 + tx;
        tile[ty + r*8][tx] = g_h[((size_t)b*CC + c)*HH + f];
    }
    __syncthreads();
    #pragma unroll
    for (int r = 0; r < 4; r++){
        int f = f0 + ty + r*8;
        int c = c0 + tx;
        g_BH[((size_t)b*HH + f)*CC + c] = __float2bfloat16(tile[tx][ty + r*8]);
    }
}

__global__ void mask_init_kernel(){
    int i = blockIdx.x*blockDim.x + threadIdx.x;
    if (i < CC) g_mask[i] = 0;
}
__global__ void mask_set_kernel(const int* __restrict__ cells, int n){
    int i = blockIdx.x*blockDim.x + threadIdx.x;
    if (i < n) g_mask[cells[i]] = 1;
}

__global__ void wconv_kernel(const float* __restrict__ W, __nv_bfloat16* w, int K, int N){
    int idx = blockIdx.x*blockDim.x + threadIdx.x;
    if (idx >= N*K) return;
    int n = idx / K, k = idx - n*K;
    w[idx] = __float2bfloat16(W[(size_t)k*N + n]);
}

// Wmh[n][k] = sum_j Wmerge[k][j] * Whh[j][n]; bias2[n] = sum_j bm[j]*Whh[j][n] + bhh[n]
__global__ void compose_kernel(const float* __restrict__ Wm, const float* __restrict__ Whh,
                               const float* __restrict__ bm, const float* __restrict__ bhh){
    int idx = blockIdx.x*blockDim.x + threadIdx.x;
    if (idx < 384*256){
        int n = idx >> 8, k = idx & 255;
        float s = 0.f;
        #pragma unroll 8
        for (int j = 0; j < 128; j++) s += Wm[k*128 + j]*Whh[(size_t)j*384 + n];
        g_Wmh[(size_t)n*256 + k] = __float2bfloat16(s);
    }
    if (idx < 384){
        float s = bhh[idx];
        for (int j = 0; j < 128; j++) s += bm[j]*Whh[(size_t)j*384 + idx];
        g_bias2[idx] = s;
    }
}

__global__ void bias_copy_kernel(const float* initb, const float* fef, const float* feb,
                                 const float* fwd, const float* bwd, const float* merge,
                                 const float* bih){
    int i = blockIdx.x*blockDim.x + threadIdx.x;
    if (i < 128){
        g_bias[OFF_INIT + i] = initb[i];
        g_bias[OFF_FWD + i]  = fwd[i];
        g_bias[OFF_BWD + i]  = bwd[i];
        g_bias[OFF_MERGE + i]= merge[i];
    }
    if (i < 32){
        g_bias[OFF_FEF + i] = fef[i];
        g_bias[OFF_FEB + i] = feb[i];
    }
    if (i < 384) g_bias[OFF_BIH + i] = bih[i];
}

// ================ x-propagation: Zx = L @ BX  (M=128, N=64) ================
#define PX_BUFSZ (16384 + 64*128)
#define PX_SMEM  (2*PX_BUFSZ)

__global__ void __launch_bounds__(256) propx_kernel(){
    constexpr int NB = 64;
    constexpr int NCC = NB/32;
    constexpr int TOTAL = 1024 + NB*8;
    extern __shared__ char smem[];
    unsigned smem_base = smem_u32(smem);
    int tid = threadIdx.x;
    int b = blockIdx.x;
    int mtile = blockIdx.y;
    int t = blockIdx.z >> 1;
    int dir = blockIdx.z & 1;

    const __nv_bfloat16* L = (dir ? g_Lb : g_Lf) + (size_t)t*CC*CC + (size_t)mtile*128*CC;
    const __nv_bfloat16* Bsrc = g_BX + (size_t)(b*TT + t)*FIN*CC;
    __nv_bfloat16* Zdst = (dir ? g_Zxb : g_Zxf) + ((size_t)t*ROWS + b*CC + mtile*128)*64;

    int wid = tid >> 5, lane = tid & 31;
    int m0 = (wid >> 1)*32;
    int n0 = (wid & 1)*(NB/2);
    int lrow = lane & 7, lq8 = (lane >> 3) & 1, lkhi = lane >> 4;

    float acc[2][NCC][2][4];
    #pragma unroll
    for (int mi = 0; mi < 2; mi++)
        #pragma unroll
        for (int nc = 0; nc < NCC; nc++)
            #pragma unroll
            for (int sb = 0; sb < 2; sb++)
                #pragma unroll
                for (int q = 0; q < 4; q++) acc[mi][nc][sb][q] = 0.f;

    {
        #pragma unroll
        for (int it = 0; it < TOTAL/256; it++){
            int idx = tid + it*256;
            const __nv_bfloat16* src; unsigned sec; int row, col;
            if (idx < 1024){ row = idx >> 3; col = idx & 7; src = L + (size_t)row*CC + col*8; sec = 0; }
            else { int i2 = idx - 1024; row = i2 >> 3; col = i2 & 7; src = Bsrc + (size_t)row*CC + col*8; sec = 16384; }
            cp16(smem_base + sec + swz(row*128 + col*16), src);
        }
        CP_COMMIT();
    }

    for (int s = 0; s < 16; s++){
        int buf = s & 1;
        if (s + 1 < 16){
            int k0 = (s+1)*64;
            unsigned base = smem_base + (buf^1)*PX_BUFSZ;
            #pragma unroll
            for (int it = 0; it < TOTAL/256; it++){
                int idx = tid + it*256;
                const __nv_bfloat16* src; unsigned sec; int row, col;
                if (idx < 1024){ row = idx >> 3; col = idx & 7; src = L + (size_t)row*CC + k0 + col*8; sec = 0; }
                else { int i2 = idx - 1024; row = i2 >> 3; col = i2 & 7; src = Bsrc + (size_t)row*CC + k0 + col*8; sec = 16384; }
                cp16(base + sec + swz(row*128 + col*16), src);
            }
            CP_COMMIT();
            asm volatile("cp.async.wait_group 1;" ::: "memory");
        } else {
            CP_WAIT0();
        }
        __syncthreads();

        unsigned ab = smem_base + buf*PX_BUFSZ;
        #pragma unroll
        for (int kk = 0; kk < 4; kk++){
            unsigned a[2][4];
            #pragma unroll
            for (int mi = 0; mi < 2; mi++){
                unsigned row = m0 + mi*16 + lrow + lq8*8;
                unsigned sw = swz(row*128 + kk*32 + lkhi*16);
                ldsm4(a[mi][0], a[mi][1], a[mi][2], a[mi][3], ab + sw);
            }
            #pragma unroll
            for (int nc = 0; nc < NCC; nc++){
                unsigned row = n0 + nc*16 + lrow + lq8*8;
                unsigned sw = swz(row*128 + kk*32 + lkhi*16);
                unsigned bh[4];
                ldsm4(bh[0], bh[1], bh[2], bh[3], ab + 16384 + sw);
                #pragma unroll
                for (int mi = 0; mi < 2; mi++){
                    mma16816(acc[mi][nc][0], a[mi], bh[0], bh[2]);
                    mma16816(acc[mi][nc][1], a[mi], bh[1], bh[3]);
                }
            }
        }
        __syncthreads();
    }

    int g = lane >> 2, cpair = (lane & 3)*2;
    #pragma unroll
    for (int mi = 0; mi < 2; mi++){
        int row = m0 + mi*16 + g;
        #pragma unroll
        for (int nc = 0; nc < NCC; nc++){
            #pragma unroll
            for (int sb = 0; sb < 2; sb++){
                int col = n0 + nc*16 + sb*8 + cpair;
                float* cc = acc[mi][nc][sb];
                *(__nv_bfloat162*)(Zdst + (size_t)row*64 + col) =
                    __floats2bfloat162_rn(cc[0], cc[1]);
                *(__nv_bfloat162*)(Zdst + (size_t)(row+8)*64 + col) =
                    __floats2bfloat162_rn(cc[2], cc[3]);
            }
        }
    }
}

// ================ h-propagation: Zh = L @ BH  (M=64 rows/CTA, N=128) ================
#define PH_BUFSZ (8192 + 16384)
#define PH_SMEM  (2*PH_BUFSZ)

__global__ void __launch_bounds__(256) proph_kernel(int t){
    extern __shared__ char smem[];
    unsigned smem_base = smem_u32(smem);
    int tid = threadIdx.x;
    int b = blockIdx.x;
    int mtile = blockIdx.y & 15;
    int dir = blockIdx.y >> 4;

    const __nv_bfloat16* L = (dir ? g_Lb : g_Lf) + (size_t)t*CC*CC + (size_t)mtile*64*CC;
    const __nv_bfloat16* Bsrc = g_BH + (size_t)b*HH*CC;
    __nv_bfloat16* Zdst = (dir ? g_Zhb : g_Zhf) + ((size_t)(b*CC + mtile*64))*HH;

    int wid = tid >> 5, lane = tid & 31;
    int m0 = (wid & 1)*32;
    int n0 = (wid >> 1)*32;
    int lrow = lane & 7, lq8 = (lane >> 3) & 1, lkhi = lane >> 4;

    float acc[2][2][2][4];
    #pragma unroll
    for (int mi = 0; mi < 2; mi++)
        #pragma unroll
        for (int nc = 0; nc < 2; nc++)
            #pragma unroll
            for (int sb = 0; sb < 2; sb++)
                #pragma unroll
                for (int q = 0; q < 4; q++) acc[mi][nc][sb][q] = 0.f;

    {
        #pragma unroll
        for (int it = 0; it < 6; it++){
            int idx = tid + it*256;
            const __nv_bfloat16* src; unsigned sec; int row, col;
            if (idx < 512){ row = idx >> 3; col = idx & 7; src = L + (size_t)row*CC + col*8; sec = 0; }
            else { int i2 = idx - 512; row = i2 >> 3; col = i2 & 7; src = Bsrc + (size_t)row*CC + col*8; sec = 8192; }
            cp16(smem_base + sec + swz(row*128 + col*16), src);
        }
        CP_COMMIT();
    }

    for (int s = 0; s < 16; s++){
        int buf = s & 1;
        if (s + 1 < 16){
            int k0 = (s+1)*64;
            unsigned base = smem_base + (buf^1)*PH_BUFSZ;
            #pragma unroll
            for (int it = 0; it < 6; it++){
                int idx = tid + it*256;
                const __nv_bfloat16* src; unsigned sec; int row, col;
                if (idx < 512){ row = idx >> 3; col = idx & 7; src = L + (size_t)row*CC + k0 + col*8; sec = 0; }
                else { int i2 = idx - 512; row = i2 >> 3; col = i2 & 7; src = Bsrc + (size_t)row*CC + k0 + col*8; sec = 8192; }
                cp16(base + sec + swz(row*128 + col*16), src);
            }
            CP_COMMIT();
            asm volatile("cp.async.wait_group 1;" ::: "memory");
        } else {
            CP_WAIT0();
        }
        __syncthreads();

        unsigned ab = smem_base + buf*PH_BUFSZ;
        #pragma unroll
        for (int kk = 0; kk < 4; kk++){
            unsigned a[2][4];
            #pragma unroll
            for (int mi = 0; mi < 2; mi++){
                unsigned row = m0 + mi*16 + lrow + lq8*8;
                unsigned sw = swz(row*128 + kk*32 + lkhi*16);
                ldsm4(a[mi][0], a[mi][1], a[mi][2], a[mi][3], ab + sw);
            }
            #pragma unroll
            for (int nc = 0; nc < 2; nc++){
                unsigned row = n0 + nc*16 + lrow + lq8*8;
                unsigned sw = swz(row*128 + kk*32 + lkhi*16);
                unsigned bh[4];
                ldsm4(bh[0], bh[1], bh[2], bh[3], ab + 8192 + sw);
                #pragma unroll
                for (int mi = 0; mi < 2; mi++){
                    mma16816(acc[mi][nc][0], a[mi], bh[0], bh[2]);
                    mma16816(acc[mi][nc][1], a[mi], bh[1], bh[3]);
                }
            }
        }
        __syncthreads();
    }

    int g = lane >> 2, cpair = (lane & 3)*2;
    #pragma unroll
    for (int mi = 0; mi < 2; mi++){
        int row = m0 + mi*16 + g;
        #pragma unroll
        for (int nc = 0; nc < 2; nc++){
            #pragma unroll
            for (int sb = 0; sb < 2; sb++){
                int col = n0 + nc*16 + sb*8 + cpair;
                float* cc = acc[mi][nc][sb];
                *(__nv_bfloat162*)(Zdst + (size_t)row*HH + col) =
                    __floats2bfloat162_rn(cc[0], cc[1]);
                *(__nv_bfloat162*)(Zdst + (size_t)(row+8)*HH + col) =
                    __floats2bfloat162_rn(cc[2], cc[3]);
            }
        }
    }
}

// ================ generic bf16 HMMA GEMM (task table) ================
// Loop tasks: 0=fwd, 1=bwd, 2=hs(gcat@Wmerge), 3..5=gh chunks (gcat@Wmh_j)
// Precompute: 10=feF, 11=feB, 12/13=gi, 14=init
#define SG_BUFSZ 40960
#define SG_SMEM  (2*SG_BUFSZ)

__global__ void __launch_bounds__(256) sgemm_kernel(int basecfg){
    int which = basecfg + blockIdx.y;
    const __nv_bfloat16 *A, *W;
    int lda, K, N, ldc, act = 0;
    const float* bias;
    float* Cf = nullptr;
    __nv_bfloat16 *Cbf = nullptr;

    switch (which){
    case 0: A=g_Zhf; lda=128; K=128; W=g_Wfwd; N=128; bias=g_bias+OFF_FWD;
            Cbf=g_gcat; ldc=256; act=1; break;
    case 1: A=g_Zhb; lda=128; K=128; W=g_Wbwd; N=128; bias=g_bias+OFF_BWD;
            Cbf=g_gcat+128; ldc=256; act=1; break;
    case 2: A=g_gcat; lda=256; K=256; W=g_Wmerge; N=128; bias=g_bias+OFF_MERGE;
            Cf=g_hsf; ldc=128; break;
    case 3: case 4: case 5: {
        int j = which - 3;
        A=g_gcat; lda=256; K=256; W=g_Wmh + (size_t)j*128*256; N=128;
        bias=g_bias2 + j*128; Cf=g_gh + j*128; ldc=384; break; }
    case 10: A=g_Zxf; lda=64; K=64; W=g_WfeF; N=32; bias=g_bias+OFF_FEF;
            Cbf=g_tmp; ldc=64; act=1; break;
    case 11: A=g_Zxb; lda=64; K=64; W=g_WfeB; N=32; bias=g_bias+OFF_FEB;
            Cbf=g_tmp+32; ldc=64; act=1; break;
    case 12: case 13: {
        int j = which - 12;
        A=g_tmp; lda=64; K=64; W=g_Wih + j*192*64; N=192; bias=g_bias+OFF_BIH+j*192;
        Cbf=g_gi_all + j*192; ldc=384; break; }
    default: // 14: init
        A=g_Zxf; lda=64; K=64; W=g_Winit; N=128; bias=g_bias+OFF_INIT;
        Cf=g_h; ldc=128; act=1; break;
    }

    extern __shared__ char smem[];
    unsigned smem_base = smem_u32(smem);
    int tid = threadIdx.x;
    int mtile = blockIdx.x;
    int wid = tid >> 5, lane = tid & 31;
    int m0 = (wid >> 1)*32;
    int Nw = N >> 1;
    int n0 = (wid & 1)*Nw;
    int ncCount = Nw >> 4; if (ncCount < 1) ncCount = 1;
    int lrow = lane & 7, lq8 = (lane >> 3) & 1, lkhi = lane >> 4;
    int nstages = K >> 6;

    float acc[2][6][2][4];
    #pragma unroll
    for (int mi = 0; mi < 2; mi++)
        #pragma unroll
        for (int nc = 0; nc < 6; nc++)
            #pragma unroll
            for (int sb = 0; sb < 2; sb++)
                #pragma unroll
                for (int q = 0; q < 4; q++) acc[mi][nc][sb][q] = 0.f;

    int total = 1024 + N*8;
    for (int idx = tid; idx < total; idx += 256){
        const __nv_bfloat16* src; unsigned sec; int row, col;
        if (idx < 1024){ row = idx >> 3; col = idx & 7;
            src = A + ((size_t)mtile*128 + row)*lda + col*8; sec = 0; }
        else { int i2 = idx - 1024; row = i2 >> 3; col = i2 & 7;
            src = W + (size_t)row*K + col*8; sec = 16384; }
        cp16(smem_base + sec + swz(row*128 + col*16), src);
    }
    CP_COMMIT();

    for (int s = 0; s < nstages; s++){
        int buf = s & 1;
        if (s + 1 < nstages){
            int k0 = (s+1)*64;
            unsigned base = smem_base + (buf^1)*SG_BUFSZ;
            for (int idx = tid; idx < total; idx += 256){
                const __nv_bfloat16* src; unsigned sec; int row, col;
                if (idx < 1024){ row = idx >> 3; col = idx & 7;
                    src = A + ((size_t)mtile*128 + row)*lda + k0 + col*8; sec = 0; }
                else { int i2 = idx - 1024; row = i2 >> 3; col = i2 & 7;
                    src = W + (size_t)row*K + k0 + col*8; sec = 16384; }
                cp16(base + sec + swz(row*128 + col*16), src);
            }
            CP_COMMIT();
            asm volatile("cp.async.wait_group 1;" ::: "memory");
        } else {
            CP_WAIT0();
        }
        __syncthreads();

        unsigned ab = smem_base + buf*SG_BUFSZ;
        #pragma unroll
        for (int kk = 0; kk < 4; kk++){
            unsigned a[2][4];
            #pragma unroll
            for (int mi = 0; mi < 2; mi++){
                unsigned row = m0 + mi*16 + lrow + lq8*8;
                unsigned sw = swz(row*128 + kk*32 + lkhi*16);
                ldsm4(a[mi][0], a[mi][1], a[mi][2], a[mi][3], ab + sw);
            }
            for (int nc = 0; nc < ncCount; nc++){
                unsigned row = n0 + nc*16 + lrow + lq8*8;
                unsigned sw = swz(row*128 + kk*32 + lkhi*16);
                unsigned bh[4];
                ldsm4(bh[0], bh[1], bh[2], bh[3], ab + 16384 + sw);
                #pragma unroll
                for (int mi = 0; mi < 2; mi++){
                    mma16816(acc[mi][nc][0], a[mi], bh[0], bh[2]);
                    mma16816(acc[mi][nc][1], a[mi], bh[1], bh[3]);
                }
            }
        }
        __syncthreads();
    }

    int g = lane >> 2, cpair = (lane & 3)*2;
    #pragma unroll
    for (int mi = 0; mi < 2; mi++){
        int row = mtile*128 + m0 + mi*16 + g;
        for (int nc = 0; nc < ncCount; nc++){
            #pragma unroll
            for (int sb = 0; sb < 2; sb++){
                int col = n0 + nc*16 + sb*8 + cpair;
                float b0 = bias[col], b1 = bias[col+1];
                float* cc = acc[mi][nc][sb];
                float v00 = cc[0] + b0, v01 = cc[1] + b1;
                float v10 = cc[2] + b0, v11 = cc[3] + b1;
                if (act){
                    v00 = fmaxf(v00, 0.f); v01 = fmaxf(v01, 0.f);
                    v10 = fmaxf(v10, 0.f); v11 = fmaxf(v11, 0.f);
                }
                if (Cf){
                    *(float2*)(Cf + (size_t)row*ldc + col)     = make_float2(v00, v01);
                    *(float2*)(Cf + (size_t)(row+8)*ldc + col) = make_float2(v10, v11);
                }
                if (Cbf){
                    *(__nv_bfloat162*)(Cbf + (size_t)row*ldc + col)     = __floats2bfloat162_rn(v00, v01);
                    *(__nv_bfloat162*)(Cbf + (size_t)(row+8)*ldc + col) = __floats2bfloat162_rn(v10, v11);
                }
            }
        }
    }
}

// ---------------- fused GRU gates + h transpose + history ----------------
__global__ void gru_tr_kernel(int t){
    __shared__ float tile[32][33];
    int c0 = blockIdx.x*32, f0 = blockIdx.y*32;
    int b = blockIdx.z;
    int tx = threadIdx.x, ty = threadIdx.y;
    #pragma unroll
    for (int r = 0; r < 4; r++){
        int cl = ty + r*8;
        size_t row = (size_t)b*CC + c0 + cl;
        int f = f0 + tx;
        const __nv_bfloat16* gi = g_gi_all + ((size_t)t*ROWS + row)*384;
        const float* gh = g_gh + row*384;
        float ir = __bfloat162float(gi[f]);
        float iz = __bfloat162float(gi[128 + f]);
        float inn = __bfloat162float(gi[256 + f]);
        float hr = gh[f], hz = gh[128 + f], hn  = gh[256 + f];
        float rg = 1.f / (1.f + expf(-(ir + hr)));
        float zg = 1.f / (1.f + expf(-(iz + hz)));
        float ng = tanhf(inn + rg*hn);
        float hs = g_hsf[row*HH + f];
        float h = (1.f - zg)*ng + zg*hs;
        tile[cl][tx] = h;
        if (t >= 4) g_hist[((size_t)(t-4)*ROWS + row)*HH + f] = h;
    }
    __syncthreads();
    #pragma unroll
    for (int r = 0; r < 4; r++){
        int fl = ty + r*8;
        int f = f0 + fl, c = c0 + tx;
        g_BH[((size_t)b*HH + f)*CC + c] = __float2bfloat16(tile[tx][fl]);
    }
}

// ---------------- final: pred = hist @ outW + outb, fused mask-scatter ----------------
__global__ void __launch_bounds__(256) predout_kernel(const float* __restrict__ in,
                                                      const float* __restrict__ outW,
                                                      const float* __restrict__ outb,
                                                      float* __restrict__ out){
    __shared__ float Ws[128*32];
    __shared__ float As[64*128];
    int r0 = blockIdx.x*64;
    int tid = threadIdx.x;
    for (int i = tid; i < 128*32; i += 256) Ws[i] = outW[i];
    {
        const float4* src = (const float4*)(g_hist + (size_t)r0*HH);
        float4* dst = (float4*)As;
        for (int i = tid; i < 64*128/4; i += 256) dst[i] = src[i];
    }
    __syncthreads();

    #pragma unroll
    for (int it = 0; it < 2; it++){
        int item = tid + it*256;
        int rl = item >> 3;
        int cg = (item & 7)*4;
        float a0 = outb[cg], a1 = outb[cg+1], a2 = outb[cg+2], a3 = outb[cg+3];
        const float* Ar = As + rl*128;
        #pragma unroll 8
        for (int k = 0; k < 128; k++){
            float av = Ar[k];
            const float* wr = Ws + k*32 + cg;
            a0 += av*wr[0]; a1 += av*wr[1]; a2 += av*wr[2]; a3 += av*wr[3];
        }
        int r = r0 + rl;
        int t = r >> 13;
        int rb = r & 8191;
        int b = rb >> 10, c = rb & 1023;
        float4 v;
        if (g_mask[c])
            v = *(const float4*)(in + (((size_t)(b*TT + t + 5)*CC + c)*160) + cg);
        else
            v = make_float4(a0, a1, a2, a3);
        *(float4*)(out + (((size_t)(b*SS + t)*CC + c)*DST) + cg) = v;
    }
}

// ---------------- host orchestration ----------------
static __nv_bfloat16* symb(const void* s){ void* p = nullptr; cudaGetSymbolAddress(&p, s); return (__nv_bfloat16*)p; }

extern "C" void kernel_launch(void* const* d_in, const int* in_sizes, int n_in,
                              void* d_out, int out_size)
{
    const float* inputs   = (const float*)d_in[0];
    const float* adj      = (const float*)d_in[1];
    const float* init_W   = (const float*)d_in[2];
    const float* init_b   = (const float*)d_in[3];
    const float* fe_fwd_W = (const float*)d_in[4];
    const float* fe_fwd_b = (const float*)d_in[5];
    const float* fe_bwd_W = (const float*)d_in[6];
    const float* fe_bwd_b = (const float*)d_in[7];
    const float* fwd_W    = (const float*)d_in[8];
    const float* fwd_b    = (const float*)d_in[9];
    const float* bwd_W    = (const float*)d_in[10];
    const float* bwd_b    = (const float*)d_in[11];
    const float* merge_W  = (const float*)d_in[12];
    const float* merge_b  = (const float*)d_in[13];
    const float* gru_Wih  = (const float*)d_in[14];
    const float* gru_bih  = (const float*)d_in[15];
    const float* gru_Whh  = (const float*)d_in[16];
    const float* gru_bhh  = (const float*)d_in[17];
    const float* out_W    = (const float*)d_in[18];
    const float* out_b    = (const float*)d_in[19];
    const int*   cells    = (const int*)  d_in[20];
    float* out = (float*)d_out;

    cudaFuncSetAttribute(propx_kernel, cudaFuncAttributeMaxDynamicSharedMemorySize, PX_SMEM);
    cudaFuncSetAttribute(proph_kernel, cudaFuncAttributeMaxDynamicSharedMemorySize, PH_SMEM);
    cudaFuncSetAttribute(sgemm_kernel, cudaFuncAttributeMaxDynamicSharedMemorySize, SG_SMEM);

    // ---- prolog ----
    rowsum_kernel<<<TT*CC/8, 256>>>(adj);
    colsum_kernel<<<dim3(4, TT), 256>>>(adj);
    build_L_kernel<<<dim3(CC/32, CC/32, TT), dim3(32, 8)>>>(adj);
    build_BX_kernel<<<dim3(CC/32, FIN/32, BB*TT), dim3(32, 8)>>>(inputs);
    mask_init_kernel<<<4, 256>>>();
    int nic = in_sizes[20];
    mask_set_kernel<<<(nic + 255)/256, 256>>>(cells, nic);

    wconv_kernel<<<(128*64 + 255)/256, 256>>>(init_W,  symb(g_Winit), 64, 128);
    wconv_kernel<<<(32*64 + 255)/256, 256>>>(fe_fwd_W, symb(g_WfeF),  64, 32);
    wconv_kernel<<<(32*64 + 255)/256, 256>>>(fe_bwd_W, symb(g_WfeB),  64, 32);
    wconv_kernel<<<(128*128 + 255)/256, 256>>>(fwd_W,  symb(g_Wfwd),  128, 128);
    wconv_kernel<<<(128*128 + 255)/256, 256>>>(bwd_W,  symb(g_Wbwd),  128, 128);
    wconv_kernel<<<(128*256 + 255)/256, 256>>>(merge_W,symb(g_Wmerge),256, 128);
    wconv_kernel<<<(384*64 + 255)/256, 256>>>(gru_Wih, symb(g_Wih),   64, 384);
    compose_kernel<<<(384*256 + 255)/256, 256>>>(merge_W, gru_Whh, merge_b, gru_bhh);
    bias_copy_kernel<<<2, 256>>>(init_b, fe_fwd_b, fe_bwd_b, fwd_b, bwd_b, merge_b,
                                 gru_bih);

    // ---- x-dependent precompute ----
    propx_kernel<<<dim3(BB, 8, NT*2), 256, PX_SMEM>>>();
    sgemm_kernel<<<dim3(NT*64, 2), 256, SG_SMEM>>>(10);   // fe fwd+bwd -> tmp
    sgemm_kernel<<<dim3(NT*64, 2), 256, SG_SMEM>>>(12);   // gi
    sgemm_kernel<<<dim3(64, 1), 256, SG_SMEM>>>(14);      // hidden0
    transpose_h_kernel<<<dim3(CC/32, HH/32, BB), dim3(32, 8)>>>();

    // ---- scan: 4 kernels per step, hs+gh parallel ----
    for (int t = 0; t < NT; t++){
        proph_kernel<<<dim3(BB, 32), 256, PH_SMEM>>>(t);
        sgemm_kernel<<<dim3(64, 2), 256, SG_SMEM>>>(0);   // fwd, bwd -> gcat
        sgemm_kernel<<<dim3(64, 4), 256, SG_SMEM>>>(2);   // hs + gh(3 chunks), one launch
        gru_tr_kernel<<<dim3(32, 4, BB), dim3(32, 8)>>>(t);
    }

    // ---- output ----
    predout_kernel<<<SS*ROWS/64, 256>>>(inputs, out_W, out_b, out);
}